// round 9
// baseline (speedup 1.0000x reference)
#include <cuda_runtime.h>
#include <cuda_bf16.h>
#include <math.h>

#define NB 4
#define ND 128
#define NT 4096
#define NK 64
#define NV 128

__device__ float g_W[256 * 128];
__device__ float g_bias[256];
__device__ __nv_bfloat16 g_QKb[NB * NT * 128];  // per row: [Q(64)|K(64)] bf16
__device__ __nv_bfloat16 g_Vb[NB * NT * 128];   // V bf16 (raw)
__device__ float g_colsum[NB * NT];
__device__ float g_inv[NB * NT];                // 1/(8*colsum)
__device__ float g_read[NB * 2048 * 128];       // split-K partial sums (q rows 2048..4095)

// ---------------------------------------------------------------------------
__device__ __forceinline__ void mma8(float* d, const unsigned* a, const unsigned* b) {
    asm volatile(
        "mma.sync.aligned.m16n8k8.row.col.f32.tf32.tf32.f32 "
        "{%0,%1,%2,%3}, {%4,%5,%6,%7}, {%8,%9}, {%0,%1,%2,%3};\n"
        : "+f"(d[0]), "+f"(d[1]), "+f"(d[2]), "+f"(d[3])
        : "r"(a[0]), "r"(a[1]), "r"(a[2]), "r"(a[3]), "r"(b[0]), "r"(b[1]));
}
__device__ __forceinline__ void mma16(float* d, const unsigned* a, const unsigned* b) {
    asm volatile(
        "mma.sync.aligned.m16n8k16.row.col.f32.bf16.bf16.f32 "
        "{%0,%1,%2,%3}, {%4,%5,%6,%7}, {%8,%9}, {%0,%1,%2,%3};\n"
        : "+f"(d[0]), "+f"(d[1]), "+f"(d[2]), "+f"(d[3])
        : "r"(a[0]), "r"(a[1]), "r"(a[2]), "r"(a[3]), "r"(b[0]), "r"(b[1]));
}
__device__ __forceinline__ unsigned packbf(float lo, float hi) {
    unsigned r;
    asm("cvt.rn.bf16x2.f32 %0, %1, %2;" : "=r"(r) : "f"(hi), "f"(lo));
    return r;
}
__device__ __forceinline__ void ldsm4(unsigned* r, unsigned addr) {
    asm volatile("ldmatrix.sync.aligned.m8n8.x4.shared.b16 {%0,%1,%2,%3}, [%4];"
                 : "=r"(r[0]), "=r"(r[1]), "=r"(r[2]), "=r"(r[3]) : "r"(addr));
}
__device__ __forceinline__ void ldsm4t(unsigned* r, unsigned addr) {
    asm volatile("ldmatrix.sync.aligned.m8n8.x4.trans.shared.b16 {%0,%1,%2,%3}, [%4];"
                 : "=r"(r[0]), "=r"(r[1]), "=r"(r[2]), "=r"(r[3]) : "r"(addr));
}
__device__ __forceinline__ void cpa16(unsigned saddr, const void* gsrc) {
    asm volatile("cp.async.cg.shared.global [%0], [%1], 16;" :: "r"(saddr), "l"(gsrc));
}
__device__ __forceinline__ void cpcommit() { asm volatile("cp.async.commit_group;"); }
template <int N>
__device__ __forceinline__ void cpwait() { asm volatile("cp.async.wait_group %0;" :: "n"(N)); }
__device__ __forceinline__ unsigned fas(float x) { return __float_as_uint(x); }
__device__ __forceinline__ unsigned ldu32(const __nv_bfloat16* p) { return *(const unsigned*)p; }

// ---------------------------------------------------------------------------
__global__ void prep_kernel(const float* __restrict__ Wk, const float* __restrict__ bk,
                            const float* __restrict__ Wq, const float* __restrict__ bq,
                            const float* __restrict__ Wv, const float* __restrict__ bv) {
    int i = blockIdx.x * blockDim.x + threadIdx.x;   // [0, 16384)
    if (i < 64 * 128) { g_W[i] = Wq[i]; g_W[64 * 128 + i] = Wk[i]; }
    g_W[128 * 128 + i] = Wv[i];
    if (i < 64) { g_bias[i] = bq[i]; g_bias[64 + i] = bk[i]; }
    if (i < 128) g_bias[128 + i] = bv[i];
    if (i < NB * NT) g_colsum[i] = 0.0f;
}

// ---------------------------------------------------------------------------
// QKV via tf32 mma. n<128 -> bf16 Q|K;  n>=128 -> bf16 V (raw).
__global__ __launch_bounds__(256) void qkv_kernel(const float* __restrict__ mb) {
    __shared__ float Xs[64 * 68];
    __shared__ float Ws[64 * 68];
    int n0 = blockIdx.x * 64, m0 = blockIdx.y * 64;
    int b = m0 >> 12, t0 = m0 & (NT - 1);
    const float* x = mb + (size_t)b * ND * NT;
    int tid = threadIdx.x, lane = tid & 31, w = tid >> 5;
    int g = lane >> 2, tg = lane & 3;
    int wr = w & 3, wc = w >> 2;
    float acc[4][4] = {};

    for (int k0 = 0; k0 < 128; k0 += 64) {
        __syncthreads();
#pragma unroll
        for (int i = 0; i < 16; i++) {
            int idx = tid + 256 * i;
            int r = idx & 63, d = idx >> 6;
            Xs[r * 68 + d] = x[(k0 + d) * NT + t0 + r];
        }
#pragma unroll
        for (int i = 0; i < 16; i++) {
            int idx = tid + 256 * i;
            int dd = idx & 63, n = idx >> 6;
            Ws[n * 68 + dd] = g_W[(n0 + n) * 128 + k0 + dd];
        }
        __syncthreads();
#pragma unroll
        for (int kk = 0; kk < 8; kk++) {
            unsigned a[4];
            a[0] = fas(Xs[(wr * 16 + g) * 68 + kk * 8 + tg]);
            a[1] = fas(Xs[(wr * 16 + g + 8) * 68 + kk * 8 + tg]);
            a[2] = fas(Xs[(wr * 16 + g) * 68 + kk * 8 + tg + 4]);
            a[3] = fas(Xs[(wr * 16 + g + 8) * 68 + kk * 8 + tg + 4]);
#pragma unroll
            for (int ni = 0; ni < 4; ni++) {
                unsigned b2[2];
                b2[0] = fas(Ws[(wc * 32 + ni * 8 + g) * 68 + kk * 8 + tg]);
                b2[1] = fas(Ws[(wc * 32 + ni * 8 + g) * 68 + kk * 8 + tg + 4]);
                mma8(acc[ni], a, b2);
            }
        }
    }
#pragma unroll
    for (int ni = 0; ni < 4; ni++) {
        int n = n0 + wc * 32 + ni * 8 + 2 * tg;   // even
        float b0 = g_bias[n], b1 = g_bias[n + 1];
        int r1 = m0 + wr * 16 + g, r2 = r1 + 8;
        if (n0 < 128) {
            *(unsigned*)&g_QKb[(size_t)r1 * 128 + n] = packbf(acc[ni][0] + b0, acc[ni][1] + b1);
            *(unsigned*)&g_QKb[(size_t)r2 * 128 + n] = packbf(acc[ni][2] + b0, acc[ni][3] + b1);
        } else {
            *(unsigned*)&g_Vb[(size_t)r1 * 128 + n - 128] = packbf(acc[ni][0] + b0, acc[ni][1] + b1);
            *(unsigned*)&g_Vb[(size_t)r2 * 128 + n - 128] = packbf(acc[ni][2] + b0, acc[ni][3] + b1);
        }
    }
}

// ---------------------------------------------------------------------------
// colsum[b][t] = sum_{q>=t} exp(Q[q].K[t]) — bf16 mma16, ldmatrix A-frags.
__global__ __launch_bounds__(256) void colsum_kernel() {
    const int QCHUNK = 512;
    int t0 = blockIdx.x * 64, b = blockIdx.y, qlo = blockIdx.z * QCHUNK;
    if (qlo + QCHUNK - 1 < t0) return;
    __shared__ __align__(16) __nv_bfloat16 Ksm[64 * 72];
    __shared__ __align__(16) __nv_bfloat16 Qsm[2][64 * 72];
    __shared__ float cs[64];
    const __nv_bfloat16* qk = g_QKb + (size_t)b * NT * 128;
    int tid = threadIdx.x, lane = tid & 31, w = tid >> 5;
    int g = lane >> 2, tg = lane & 3, wr = w & 1, wc = w >> 1;
    unsigned sbq = (unsigned)__cvta_generic_to_shared(&Qsm[0][0]);

    { int c = tid & 7, r0 = tid >> 3;            // K tile (once)
#pragma unroll
      for (int i = 0; i < 2; i++) { int r = r0 + 32 * i;
          *(uint4*)&Ksm[r * 72 + c * 8] = *(const uint4*)&qk[(size_t)(t0 + r) * 128 + 64 + c * 8]; } }
    if (tid < 64) cs[tid] = 0.0f;
    { int c = tid & 7, r0 = tid >> 3;            // prefetch Q tile 0
#pragma unroll
      for (int i = 0; i < 2; i++) { int r = r0 + 32 * i;
          cpa16(sbq + (r * 72 + c * 8) * 2, qk + (size_t)(qlo + r) * 128 + c * 8); } }
    cpcommit();
    __syncthreads();

    unsigned bf[2][4][2];                        // hoisted K B-frags
#pragma unroll
    for (int ni = 0; ni < 2; ni++)
#pragma unroll
        for (int kk2 = 0; kk2 < 4; kk2++) {
            int n = wc * 16 + ni * 8 + g;
            bf[ni][kk2][0] = ldu32(&Ksm[n * 72 + kk2 * 16 + 2 * tg]);
            bf[ni][kk2][1] = ldu32(&Ksm[n * 72 + kk2 * 16 + 8 + 2 * tg]);
        }

    float colacc[2][2] = {};
    int buf = 0;
    int arow = (lane & 7) + ((lane >> 3) & 1) * 8;
    int acol = (lane >> 4) * 8;
    for (int q0 = qlo; q0 < qlo + QCHUNK; q0 += 64) {
        if (q0 + 64 < qlo + QCHUNK) {
            int c = tid & 7, r0 = tid >> 3, bo = buf ^ 1;
#pragma unroll
            for (int i = 0; i < 2; i++) { int r = r0 + 32 * i;
                cpa16(sbq + bo * 9216 + (r * 72 + c * 8) * 2,
                      qk + (size_t)(q0 + 64 + r) * 128 + c * 8); }
        }
        cpcommit(); cpwait<1>(); __syncthreads();
        if (q0 + 63 >= t0) {
            unsigned qbase = sbq + buf * 9216;
            float d[2][2][4] = {};
#pragma unroll
            for (int kk2 = 0; kk2 < 4; kk2++) {
                unsigned a[2][4];
#pragma unroll
                for (int mi = 0; mi < 2; mi++) {
                    int r = wr * 32 + mi * 16 + arow;
                    ldsm4(a[mi], qbase + (r * 72 + kk2 * 16 + acol) * 2);
                }
#pragma unroll
                for (int mi = 0; mi < 2; mi++)
#pragma unroll
                    for (int ni = 0; ni < 2; ni++)
                        mma16(d[mi][ni], a[mi], bf[ni][kk2]);
            }
#pragma unroll
            for (int mi = 0; mi < 2; mi++)
#pragma unroll
                for (int ni = 0; ni < 2; ni++)
#pragma unroll
                    for (int e = 0; e < 4; e++) {
                        int row = q0 + wr * 32 + mi * 16 + g + (e >> 1) * 8;
                        int col = t0 + wc * 16 + ni * 8 + 2 * tg + (e & 1);
                        if (row >= col) colacc[ni][e & 1] += __expf(d[mi][ni][e]);
                    }
        }
        __syncthreads();
        buf ^= 1;
    }
#pragma unroll
    for (int ni = 0; ni < 2; ni++)
#pragma unroll
        for (int j = 0; j < 2; j++) {
            float v = colacc[ni][j];
            v += __shfl_xor_sync(0xffffffffu, v, 4);
            v += __shfl_xor_sync(0xffffffffu, v, 8);
            v += __shfl_xor_sync(0xffffffffu, v, 16);
            colacc[ni][j] = v;
        }
    if (g == 0)
#pragma unroll
        for (int ni = 0; ni < 2; ni++) {
            atomicAdd(&cs[wc * 16 + ni * 8 + 2 * tg], colacc[ni][0]);
            atomicAdd(&cs[wc * 16 + ni * 8 + 2 * tg + 1], colacc[ni][1]);
        }
    __syncthreads();
    if (tid < 64) atomicAdd(&g_colsum[b * NT + t0 + tid], cs[tid]);
}

// ---------------------------------------------------------------------------
// inv + zero the split-K partial buffer.
__global__ void inv_kernel() {
    int i = blockIdx.x * 256 + threadIdx.x;      // [0, 1048576)
    if (i < NB * NT) g_inv[i] = 1.0f / (8.0f * g_colsum[i]);
    g_read[i] = 0.0f;
}

// ---------------------------------------------------------------------------
// attn: block handles q-tile pair (2k, 2k+1), t-chunk [tb,te).
//   xx <  32: k = 16 + (xx>>1), chunk = xx&1  (split pairs, partials -> g_read)
//   xx >= 32: k = xx - 32, full range, direct epilogue.
#define AT_KB 18432
#define AT_VB 36864
#define AT_IB 71680
#define ATT_SMEM 72192

__global__ __launch_bounds__(256) void attn_kernel(const float* __restrict__ mb,
                                                   float* __restrict__ out) {
    extern __shared__ float sm[];
    __nv_bfloat16* smb = (__nv_bfloat16*)sm;
    float* invs = (float*)((char*)sm + AT_IB);
    int xx = blockIdx.x, b = blockIdx.y;
    int k, ch; bool split;
    if (xx < 32) { k = 16 + (xx >> 1); ch = xx & 1; split = true; }
    else         { k = xx - 32;        ch = 0;      split = false; }
    int qtA = 2 * k, qtB = 2 * k + 1;
    int q0A = qtA * 64, q0B = qtB * 64;
    int tbeg = ch * 32;
    int tend = qtB + 1 < tbeg + 32 ? qtB + 1 : tbeg + 32;
    const __nv_bfloat16* qk = g_QKb + (size_t)b * NT * 128;
    const __nv_bfloat16* vsb = g_Vb + (size_t)b * NT * 128;
    const float* invp = g_inv + (size_t)b * NT;
    int tid = threadIdx.x, lane = tid & 31, w = tid >> 5;
    int g = lane >> 2, tg = lane & 3;
    int gid = w >> 2, wg = w & 3;
    int myqt = gid ? qtB : qtA;
    unsigned sb = (unsigned)__cvta_generic_to_shared(sm);

    // load both Q tiles (bf16)
#pragma unroll
    for (int i = 0; i < 4; i++) {
        int idx = tid + 256 * i;
        int grp = idx >> 9, rem = idx & 511, r = rem >> 3, c = rem & 7;
        int q0g = grp ? q0B : q0A;
        *(uint4*)&smb[grp * 4608 + r * 72 + c * 8] =
            *(const uint4*)&qk[(size_t)(q0g + r) * 128 + c * 8];
    }
    // prefetch first tile (K + V + inv)
    {
        int t0r = tbeg * 64;
#pragma unroll
        for (int i = 0; i < 2; i++) { int idx = tid + 256 * i; int r = idx >> 3, c = idx & 7;
            cpa16(sb + AT_KB + (r * 72 + c * 8) * 2, qk + (size_t)(t0r + r) * 128 + 64 + c * 8); }
#pragma unroll
        for (int i = 0; i < 4; i++) { int idx = tid + 256 * i; int r = idx >> 4, c = idx & 15;
            cpa16(sb + AT_VB + (r * 136 + c * 8) * 2, vsb + (size_t)(t0r + r) * 128 + c * 8); }
        if (tid < 16) cpa16(sb + AT_IB + tid * 16, invp + t0r + tid * 4);
    }
    cpcommit();
    __syncthreads();

    // hoist Q A-fragments (bf16, via ldmatrix)
    int arow = (lane & 7) + ((lane >> 3) & 1) * 8;
    int acol = (lane >> 4) * 8;
    unsigned qbase = sb + gid * 9216;
    unsigned qa_[4][4];
#pragma unroll
    for (int kk2 = 0; kk2 < 4; kk2++)
        ldsm4(qa_[kk2], qbase + ((wg * 16 + arow) * 72 + kk2 * 16 + acol) * 2);

    int krow = ((lane >> 4) << 3) + (lane & 7);
    int kcol = ((lane >> 3) & 1) * 8;

    float acc[16][4] = {};
    int buf = 0;
    int sub = lane >> 3, li = lane & 7;
    for (int tt = tbeg; tt < tend; tt++) {
        if (tt + 1 < tend) {
            int t1 = (tt + 1) * 64, bo = buf ^ 1;
#pragma unroll
            for (int i = 0; i < 2; i++) { int idx = tid + 256 * i; int r = idx >> 3, c = idx & 7;
                cpa16(sb + AT_KB + bo * 9216 + (r * 72 + c * 8) * 2,
                      qk + (size_t)(t1 + r) * 128 + 64 + c * 8); }
#pragma unroll
            for (int i = 0; i < 4; i++) { int idx = tid + 256 * i; int r = idx >> 4, c = idx & 15;
                cpa16(sb + AT_VB + bo * 17408 + (r * 136 + c * 8) * 2,
                      vsb + (size_t)(t1 + r) * 128 + c * 8); }
            if (tid < 16) cpa16(sb + AT_IB + bo * 256 + tid * 16, invp + t1 + tid * 4);
        }
        cpcommit(); cpwait<1>(); __syncthreads();

        if (tt <= myqt) {
            unsigned kbase = sb + AT_KB + buf * 9216;
            float d[8][4] = {};
#pragma unroll
            for (int kk2 = 0; kk2 < 4; kk2++)
#pragma unroll
                for (int nb = 0; nb < 4; nb++) {
                    unsigned r4[4];
                    ldsm4(r4, kbase + ((nb * 16 + krow) * 72 + kk2 * 16 + kcol) * 2);
                    mma16(d[nb * 2 + 0], qa_[kk2], &r4[0]);
                    mma16(d[nb * 2 + 1], qa_[kk2], &r4[2]);
                }
            bool diag = (tt == myqt);
            const float* ivt = invs + buf * 64;
            unsigned Af[4][4];
#pragma unroll
            for (int ni = 0; ni < 8; ni++) {
                float2 iv = *(const float2*)&ivt[ni * 8 + 2 * tg];
                float e[4];
#pragma unroll
                for (int c = 0; c < 4; c++) {
                    int row = wg * 16 + g + (c >> 1) * 8;
                    int col = ni * 8 + 2 * tg + (c & 1);
                    float v = __expf(d[ni][c]) * ((c & 1) ? iv.y : iv.x);
                    e[c] = (diag && col > row) ? 0.0f : v;
                }
                Af[ni >> 1][(ni & 1) * 2 + 0] = packbf(e[0], e[1]);
                Af[ni >> 1][(ni & 1) * 2 + 1] = packbf(e[2], e[3]);
            }
#pragma unroll
            for (int kc = 0; kc < 4; kc++)
#pragma unroll
                for (int nj = 0; nj < 8; nj++) {
                    unsigned r4[4];
                    unsigned addr = sb + AT_VB + buf * 17408 +
                        ((kc * 16 + (sub & 1) * 8 + li) * 136 + nj * 16 + (sub >> 1) * 8) * 2;
                    ldsm4t(r4, addr);
                    mma16(acc[nj * 2 + 0], Af[kc], &r4[0]);
                    mma16(acc[nj * 2 + 1], Af[kc], &r4[2]);
                }
        }
        __syncthreads();
        buf ^= 1;
    }

    if (split) {
        // partial accumulate into g_read (q rows all >= 2048 since k >= 16)
        int q0w = gid ? q0B : q0A;
        size_t base = (size_t)b * 2048 + (q0w - 2048);
#pragma unroll
        for (int nj = 0; nj < 16; nj++)
#pragma unroll
            for (int c = 0; c < 4; c++) {
                int row = wg * 16 + g + (c >> 1) * 8;
                int col = nj * 8 + 2 * tg + (c & 1);
                atomicAdd(&g_read[(base + row) * 128 + col], acc[nj][c]);
            }
        return;
    }

    // direct epilogue: stage (f32 stride 133), add residual, transposed write
    float* stg = gid ? (sm + 8704) : sm;
#pragma unroll
    for (int nj = 0; nj < 16; nj++)
#pragma unroll
        for (int c = 0; c < 4; c++) {
            int row = wg * 16 + g + (c >> 1) * 8;
            int col = nj * 8 + 2 * tg + (c & 1);
            stg[row * 133 + col] = acc[nj][c];
        }
    __syncthreads();
    {
        int gw = tid >> 7, gtid = tid & 127;
        int qq = gtid & 63, db = gtid >> 6;
        const float* s2 = gw ? (sm + 8704) : sm;
        int q0w = gw ? q0B : q0A;
        const float* xin = mb + (size_t)b * ND * NT;
        float* o = out + (size_t)b * ND * NT;
#pragma unroll
        for (int i = 0; i < 64; i++) {
            int d_ = db + i * 2;
            o[d_ * NT + q0w + qq] = xin[d_ * NT + q0w + qq] + s2[qq * 133 + d_];
        }
    }
}

// ---------------------------------------------------------------------------
// addback: rows 2048..4095 — out = x + g_read^T  (scalar smem stores: stride 133
// is NOT float4-aligned for odd rows; reads stay conflict-free at stride 133)
__global__ __launch_bounds__(256) void addback_kernel(const float* __restrict__ mb,
                                                      float* __restrict__ out) {
    __shared__ float s[64 * 133];
    int t0 = 2048 + blockIdx.x * 64, b = blockIdx.y;
    const float* rd = g_read + ((size_t)b * 2048 + (t0 - 2048)) * 128;
    int tid = threadIdx.x;
#pragma unroll
    for (int i = 0; i < 8; i++) {
        int idx = tid + 256 * i;                 // 0..2047
        int r = idx >> 5, c4 = idx & 31;
        float4 v = *(const float4*)&rd[r * 128 + c4 * 4];
        s[r * 133 + c4 * 4 + 0] = v.x;
        s[r * 133 + c4 * 4 + 1] = v.y;
        s[r * 133 + c4 * 4 + 2] = v.z;
        s[r * 133 + c4 * 4 + 3] = v.w;
    }
    __syncthreads();
    int qq = tid & 63, db = tid >> 6;
    const float* xin = mb + (size_t)b * ND * NT;
    float* o = out + (size_t)b * ND * NT;
#pragma unroll
    for (int i = 0; i < 32; i++) {
        int d_ = db + i * 4;
        o[d_ * NT + t0 + qq] = xin[d_ * NT + t0 + qq] + s[qq * 133 + d_];
    }
}

// ---------------------------------------------------------------------------
extern "C" void kernel_launch(void* const* d_in, const int* in_sizes, int n_in,
                              void* d_out, int out_size) {
    const float* mb = (const float*)d_in[0];
    const float* Wk = (const float*)d_in[1];
    const float* bk = (const float*)d_in[2];
    const float* Wq = (const float*)d_in[3];
    const float* bq = (const float*)d_in[4];
    const float* Wv = (const float*)d_in[5];
    const float* bv = (const float*)d_in[6];
    float* out = (float*)d_out;

    cudaFuncSetAttribute(attn_kernel, cudaFuncAttributeMaxDynamicSharedMemorySize, ATT_SMEM);

    prep_kernel<<<64, 256>>>(Wk, bk, Wq, bq, Wv, bv);
    qkv_kernel<<<dim3(4, 256), 256>>>(mb);
    colsum_kernel<<<dim3(64, 4, 8), 256>>>();
    inv_kernel<<<4096, 256>>>();
    attn_kernel<<<dim3(48, 4), 256, ATT_SMEM>>>(mb, out);
    addback_kernel<<<dim3(32, 4), 256>>>(mb, out);
}

// round 10
// speedup vs baseline: 1.1195x; 1.1195x over previous
#include <cuda_runtime.h>
#include <cuda_bf16.h>
#include <math.h>

#define NB 4
#define ND 128
#define NT 4096

__device__ float g_W[256 * 128];
__device__ float g_bias[256];
__device__ __nv_bfloat16 g_QKb[NB * NT * 128];  // per row: [Q(64)|K(64)] bf16
__device__ __nv_bfloat16 g_Vb[NB * NT * 128];   // V bf16
__device__ float g_colsum[NB * NT];
__device__ float g_inv[NB * NT];                // 1/(8*colsum)

// ---------------------------------------------------------------------------
__device__ __forceinline__ void mma8(float* d, const unsigned* a, const unsigned* b) {
    asm volatile(
        "mma.sync.aligned.m16n8k8.row.col.f32.tf32.tf32.f32 "
        "{%0,%1,%2,%3}, {%4,%5,%6,%7}, {%8,%9}, {%0,%1,%2,%3};\n"
        : "+f"(d[0]), "+f"(d[1]), "+f"(d[2]), "+f"(d[3])
        : "r"(a[0]), "r"(a[1]), "r"(a[2]), "r"(a[3]), "r"(b[0]), "r"(b[1]));
}
__device__ __forceinline__ void mma16(float* d, const unsigned* a, const unsigned* b) {
    asm volatile(
        "mma.sync.aligned.m16n8k16.row.col.f32.bf16.bf16.f32 "
        "{%0,%1,%2,%3}, {%4,%5,%6,%7}, {%8,%9}, {%0,%1,%2,%3};\n"
        : "+f"(d[0]), "+f"(d[1]), "+f"(d[2]), "+f"(d[3])
        : "r"(a[0]), "r"(a[1]), "r"(a[2]), "r"(a[3]), "r"(b[0]), "r"(b[1]));
}
__device__ __forceinline__ unsigned packbf(float lo, float hi) {
    unsigned r;
    asm("cvt.rn.bf16x2.f32 %0, %1, %2;" : "=r"(r) : "f"(hi), "f"(lo));
    return r;
}
__device__ __forceinline__ void ldsm4(unsigned* r, unsigned addr) {
    asm volatile("ldmatrix.sync.aligned.m8n8.x4.shared.b16 {%0,%1,%2,%3}, [%4];"
                 : "=r"(r[0]), "=r"(r[1]), "=r"(r[2]), "=r"(r[3]) : "r"(addr));
}
__device__ __forceinline__ void ldsm4t(unsigned* r, unsigned addr) {
    asm volatile("ldmatrix.sync.aligned.m8n8.x4.trans.shared.b16 {%0,%1,%2,%3}, [%4];"
                 : "=r"(r[0]), "=r"(r[1]), "=r"(r[2]), "=r"(r[3]) : "r"(addr));
}
__device__ __forceinline__ void cpa16(unsigned saddr, const void* gsrc) {
    asm volatile("cp.async.cg.shared.global [%0], [%1], 16;" :: "r"(saddr), "l"(gsrc));
}
__device__ __forceinline__ void cpcommit() { asm volatile("cp.async.commit_group;"); }
template <int N>
__device__ __forceinline__ void cpwait() { asm volatile("cp.async.wait_group %0;" :: "n"(N)); }
__device__ __forceinline__ void barg(int id) {
    asm volatile("bar.sync %0, 128;" :: "r"(id) : "memory");
}
__device__ __forceinline__ unsigned fas(float x) { return __float_as_uint(x); }
__device__ __forceinline__ unsigned ldu32(const __nv_bfloat16* p) { return *(const unsigned*)p; }

// ---------------------------------------------------------------------------
__global__ void prep_kernel(const float* __restrict__ Wk, const float* __restrict__ bk,
                            const float* __restrict__ Wq, const float* __restrict__ bq,
                            const float* __restrict__ Wv, const float* __restrict__ bv) {
    int i = blockIdx.x * blockDim.x + threadIdx.x;   // [0, 16384)
    if (i < 64 * 128) { g_W[i] = Wq[i]; g_W[64 * 128 + i] = Wk[i]; }
    g_W[128 * 128 + i] = Wv[i];
    if (i < 64) { g_bias[i] = bq[i]; g_bias[64 + i] = bk[i]; }
    if (i < 128) g_bias[128 + i] = bv[i];
    if (i < NB * NT) g_colsum[i] = 0.0f;
}

// ---------------------------------------------------------------------------
// QKV via tf32 mma. n<128 -> bf16 Q|K;  n>=128 -> bf16 V.
__global__ __launch_bounds__(256) void qkv_kernel(const float* __restrict__ mb) {
    __shared__ float Xs[64 * 68];
    __shared__ float Ws[64 * 68];
    int n0 = blockIdx.x * 64, m0 = blockIdx.y * 64;
    int b = m0 >> 12, t0 = m0 & (NT - 1);
    const float* x = mb + (size_t)b * ND * NT;
    int tid = threadIdx.x, lane = tid & 31, w = tid >> 5;
    int g = lane >> 2, tg = lane & 3;
    int wr = w & 3, wc = w >> 2;
    float acc[4][4] = {};

    for (int k0 = 0; k0 < 128; k0 += 64) {
        __syncthreads();
#pragma unroll
        for (int i = 0; i < 16; i++) {
            int idx = tid + 256 * i;
            int r = idx & 63, d = idx >> 6;
            Xs[r * 68 + d] = x[(k0 + d) * NT + t0 + r];
        }
#pragma unroll
        for (int i = 0; i < 16; i++) {
            int idx = tid + 256 * i;
            int dd = idx & 63, n = idx >> 6;
            Ws[n * 68 + dd] = g_W[(n0 + n) * 128 + k0 + dd];
        }
        __syncthreads();
#pragma unroll
        for (int kk = 0; kk < 8; kk++) {
            unsigned a[4];
            a[0] = fas(Xs[(wr * 16 + g) * 68 + kk * 8 + tg]);
            a[1] = fas(Xs[(wr * 16 + g + 8) * 68 + kk * 8 + tg]);
            a[2] = fas(Xs[(wr * 16 + g) * 68 + kk * 8 + tg + 4]);
            a[3] = fas(Xs[(wr * 16 + g + 8) * 68 + kk * 8 + tg + 4]);
#pragma unroll
            for (int ni = 0; ni < 4; ni++) {
                unsigned b2[2];
                b2[0] = fas(Ws[(wc * 32 + ni * 8 + g) * 68 + kk * 8 + tg]);
                b2[1] = fas(Ws[(wc * 32 + ni * 8 + g) * 68 + kk * 8 + tg + 4]);
                mma8(acc[ni], a, b2);
            }
        }
    }
#pragma unroll
    for (int ni = 0; ni < 4; ni++) {
        int n = n0 + wc * 32 + ni * 8 + 2 * tg;
        float b0 = g_bias[n], b1 = g_bias[n + 1];
        int r1 = m0 + wr * 16 + g, r2 = r1 + 8;
        if (n0 < 128) {
            *(unsigned*)&g_QKb[(size_t)r1 * 128 + n] = packbf(acc[ni][0] + b0, acc[ni][1] + b1);
            *(unsigned*)&g_QKb[(size_t)r2 * 128 + n] = packbf(acc[ni][2] + b0, acc[ni][3] + b1);
        } else {
            *(unsigned*)&g_Vb[(size_t)r1 * 128 + n - 128] = packbf(acc[ni][0] + b0, acc[ni][1] + b1);
            *(unsigned*)&g_Vb[(size_t)r2 * 128 + n - 128] = packbf(acc[ni][2] + b0, acc[ni][3] + b1);
        }
    }
}

// ---------------------------------------------------------------------------
// colsum[b][t] = sum_{q>=t} exp(Q[q].K[t]) — bf16 mma16, ldmatrix A-frags.
__global__ __launch_bounds__(256) void colsum_kernel() {
    const int QCHUNK = 512;
    int t0 = blockIdx.x * 64, b = blockIdx.y, qlo = blockIdx.z * QCHUNK;
    if (qlo + QCHUNK - 1 < t0) return;
    __shared__ __align__(16) __nv_bfloat16 Ksm[64 * 72];
    __shared__ __align__(16) __nv_bfloat16 Qsm[2][64 * 72];
    __shared__ float cs[64];
    const __nv_bfloat16* qk = g_QKb + (size_t)b * NT * 128;
    int tid = threadIdx.x, lane = tid & 31, w = tid >> 5;
    int g = lane >> 2, tg = lane & 3, wr = w & 1, wc = w >> 1;
    unsigned sbq = (unsigned)__cvta_generic_to_shared(&Qsm[0][0]);

    { int c = tid & 7, r0 = tid >> 3;
#pragma unroll
      for (int i = 0; i < 2; i++) { int r = r0 + 32 * i;
          *(uint4*)&Ksm[r * 72 + c * 8] = *(const uint4*)&qk[(size_t)(t0 + r) * 128 + 64 + c * 8]; } }
    if (tid < 64) cs[tid] = 0.0f;
    { int c = tid & 7, r0 = tid >> 3;
#pragma unroll
      for (int i = 0; i < 2; i++) { int r = r0 + 32 * i;
          cpa16(sbq + (r * 72 + c * 8) * 2, qk + (size_t)(qlo + r) * 128 + c * 8); } }
    cpcommit();
    __syncthreads();

    unsigned bf[2][4][2];
#pragma unroll
    for (int ni = 0; ni < 2; ni++)
#pragma unroll
        for (int kk2 = 0; kk2 < 4; kk2++) {
            int n = wc * 16 + ni * 8 + g;
            bf[ni][kk2][0] = ldu32(&Ksm[n * 72 + kk2 * 16 + 2 * tg]);
            bf[ni][kk2][1] = ldu32(&Ksm[n * 72 + kk2 * 16 + 8 + 2 * tg]);
        }

    float colacc[2][2] = {};
    int buf = 0;
    int arow = (lane & 7) + ((lane >> 3) & 1) * 8;
    int acol = (lane >> 4) * 8;
    for (int q0 = qlo; q0 < qlo + QCHUNK; q0 += 64) {
        if (q0 + 64 < qlo + QCHUNK) {
            int c = tid & 7, r0 = tid >> 3, bo = buf ^ 1;
#pragma unroll
            for (int i = 0; i < 2; i++) { int r = r0 + 32 * i;
                cpa16(sbq + bo * 9216 + (r * 72 + c * 8) * 2,
                      qk + (size_t)(q0 + 64 + r) * 128 + c * 8); }
        }
        cpcommit(); cpwait<1>(); __syncthreads();
        if (q0 + 63 >= t0) {
            unsigned qbase = sbq + buf * 9216;
            float d[2][2][4] = {};
#pragma unroll
            for (int kk2 = 0; kk2 < 4; kk2++) {
                unsigned a[2][4];
#pragma unroll
                for (int mi = 0; mi < 2; mi++) {
                    int r = wr * 32 + mi * 16 + arow;
                    ldsm4(a[mi], qbase + (r * 72 + kk2 * 16 + acol) * 2);
                }
#pragma unroll
                for (int mi = 0; mi < 2; mi++)
#pragma unroll
                    for (int ni = 0; ni < 2; ni++)
                        mma16(d[mi][ni], a[mi], bf[ni][kk2]);
            }
#pragma unroll
            for (int mi = 0; mi < 2; mi++)
#pragma unroll
                for (int ni = 0; ni < 2; ni++)
#pragma unroll
                    for (int e = 0; e < 4; e++) {
                        int row = q0 + wr * 32 + mi * 16 + g + (e >> 1) * 8;
                        int col = t0 + wc * 16 + ni * 8 + 2 * tg + (e & 1);
                        if (row >= col) colacc[ni][e & 1] += __expf(d[mi][ni][e]);
                    }
        }
        __syncthreads();
        buf ^= 1;
    }
#pragma unroll
    for (int ni = 0; ni < 2; ni++)
#pragma unroll
        for (int j = 0; j < 2; j++) {
            float v = colacc[ni][j];
            v += __shfl_xor_sync(0xffffffffu, v, 4);
            v += __shfl_xor_sync(0xffffffffu, v, 8);
            v += __shfl_xor_sync(0xffffffffu, v, 16);
            colacc[ni][j] = v;
        }
    if (g == 0)
#pragma unroll
        for (int ni = 0; ni < 2; ni++) {
            atomicAdd(&cs[wc * 16 + ni * 8 + 2 * tg], colacc[ni][0]);
            atomicAdd(&cs[wc * 16 + ni * 8 + 2 * tg + 1], colacc[ni][1]);
        }
    __syncthreads();
    if (tid < 64) atomicAdd(&g_colsum[b * NT + t0 + tid], cs[tid]);
}

// ---------------------------------------------------------------------------
__global__ void inv_kernel() {
    int i = blockIdx.x * 256 + threadIdx.x;
    g_inv[i] = 1.0f / (8.0f * g_colsum[i]);
}

// ---------------------------------------------------------------------------
// attn: block xx handles pair (xx, 63-xx) with INDEPENDENT per-group t-streams.
//   gid1: tile B, t=0..32 (33 iters).
//   gid0: tile A t=0..xx, mid-epilogue, then tile B t=33..63-xx (32 iters total).
// gid0's tile-B partial combined into gid1's acc via smem.
// smem bytes: [0,18432) Q both tiles; per-group region 53760 B at 18432 + gid*53760
//   (K dbuf 18432 | V dbuf 34816 @+18432 | inv dbuf 512 @+53248); staging @125952 (34048 B).
#define AT_G0 18432
#define AT_GSZ 53760
#define AT_VOFF 18432
#define AT_IOFF 53248
#define AT_ST 125952
#define ATT_SMEM 160000

__global__ __launch_bounds__(256, 1) void attn_kernel(const float* __restrict__ mb,
                                                      float* __restrict__ out) {
    extern __shared__ float sm[];
    __nv_bfloat16* smb = (__nv_bfloat16*)sm;
    float* stg = (float*)((char*)sm + AT_ST);
    int xx = blockIdx.x, b = blockIdx.y;
    int qtA = xx, qtB = 63 - xx;
    int q0A = qtA * 64, q0B = qtB * 64;
    int TA = xx + 1;
    const __nv_bfloat16* qk = g_QKb + (size_t)b * NT * 128;
    const __nv_bfloat16* vsb = g_Vb + (size_t)b * NT * 128;
    const float* invp = g_inv + (size_t)b * NT;
    int tid = threadIdx.x, lane = tid & 31, w = tid >> 5;
    int g = lane >> 2, tg = lane & 3;
    int gid = w >> 2, wg = w & 3, gtid = tid & 127;
    int mybar = gid + 1;
    unsigned sb = (unsigned)__cvta_generic_to_shared(sm);
    unsigned greg = sb + AT_G0 + gid * AT_GSZ;
    float* ginv = (float*)((char*)sm + AT_G0 + gid * AT_GSZ + AT_IOFF);

    // load both Q tiles (bf16), 256 threads
#pragma unroll
    for (int i = 0; i < 4; i++) {
        int idx = tid + 256 * i;
        int grp = idx >> 9, rem = idx & 511, r = rem >> 3, c = rem & 7;
        int q0g = grp ? q0B : q0A;
        *(uint4*)&smb[grp * 4608 + r * 72 + c * 8] =
            *(const uint4*)&qk[(size_t)(q0g + r) * 128 + c * 8];
    }

    // per-group iteration plan
    int n_iters = gid ? 33 : 32;
    // t_of(pos): gid1: pos; gid0: pos<TA ? pos : pos - TA + 33
    auto prefetch = [&](int t, int bo) {
        int t0r = t * 64;
#pragma unroll
        for (int i = 0; i < 4; i++) { int idx = gtid + 128 * i; int r = idx >> 3, c = idx & 7;
            cpa16(greg + bo * 9216 + (r * 72 + c * 8) * 2, qk + (size_t)(t0r + r) * 128 + 64 + c * 8); }
#pragma unroll
        for (int i = 0; i < 8; i++) { int idx = gtid + 128 * i; int r = idx >> 4, c = idx & 15;
            cpa16(greg + AT_VOFF + bo * 17408 + (r * 136 + c * 8) * 2,
                  vsb + (size_t)(t0r + r) * 128 + c * 8); }
        if (gtid < 16) cpa16(greg + AT_IOFF + bo * 256 + gtid * 16, invp + t0r + gtid * 4);
    };

    prefetch(0, 0);   // both groups start at t=0
    cpcommit();
    __syncthreads();  // Q visible + initial prefetch ordering

    // Q A-fragments via ldmatrix
    int arow = (lane & 7) + ((lane >> 3) & 1) * 8;
    int acol = (lane >> 4) * 8;
    unsigned qa_[4][4];
#pragma unroll
    for (int kk2 = 0; kk2 < 4; kk2++)
        ldsm4(qa_[kk2], sb + gid * 9216 + ((wg * 16 + arow) * 72 + kk2 * 16 + acol) * 2);

    int krow = ((lane >> 4) << 3) + (lane & 7);
    int kcol = ((lane >> 3) & 1) * 8;
    int sub = lane >> 3, li = lane & 7;

    float acc[16][4] = {};
    int buf = 0;
    int myqt = gid ? qtB : qtA;

    for (int pos = 0; pos < n_iters; pos++) {
        int tt = gid ? pos : (pos < TA ? pos : pos - TA + 33);
        if (pos + 1 < n_iters) {
            int tn = gid ? (pos + 1) : (pos + 1 < TA ? pos + 1 : pos + 1 - TA + 33);
            prefetch(tn, buf ^ 1);
        }
        cpcommit(); cpwait<1>(); barg(mybar);

        {
            unsigned kbase = greg + buf * 9216;
            float d[8][4] = {};
#pragma unroll
            for (int kk2 = 0; kk2 < 4; kk2++)
#pragma unroll
                for (int nb = 0; nb < 4; nb++) {
                    unsigned r4[4];
                    ldsm4(r4, kbase + ((nb * 16 + krow) * 72 + kk2 * 16 + kcol) * 2);
                    mma16(d[nb * 2 + 0], qa_[kk2], &r4[0]);
                    mma16(d[nb * 2 + 1], qa_[kk2], &r4[2]);
                }
            bool diag = (tt == myqt);
            const float* ivt = ginv + buf * 64;
            unsigned Af[4][4];
#pragma unroll
            for (int ni = 0; ni < 8; ni++) {
                float2 iv = *(const float2*)&ivt[ni * 8 + 2 * tg];
                float e[4];
#pragma unroll
                for (int c = 0; c < 4; c++) {
                    int row = wg * 16 + g + (c >> 1) * 8;
                    int col = ni * 8 + 2 * tg + (c & 1);
                    float v = __expf(d[ni][c]) * ((c & 1) ? iv.y : iv.x);
                    e[c] = (diag && col > row) ? 0.0f : v;
                }
                Af[ni >> 1][(ni & 1) * 2 + 0] = packbf(e[0], e[1]);
                Af[ni >> 1][(ni & 1) * 2 + 1] = packbf(e[2], e[3]);
            }
#pragma unroll
            for (int kc = 0; kc < 4; kc++)
#pragma unroll
                for (int nj = 0; nj < 8; nj++) {
                    unsigned r4[4];
                    unsigned addr = greg + AT_VOFF + buf * 17408 +
                        ((kc * 16 + (sub & 1) * 8 + li) * 136 + nj * 16 + (sub >> 1) * 8) * 2;
                    ldsm4t(r4, addr);
                    mma16(acc[nj * 2 + 0], Af[kc], &r4[0]);
                    mma16(acc[nj * 2 + 1], Af[kc], &r4[2]);
                }
        }

        // gid0 phase switch: tile A done -> epilogue, reset, retarget to tile B
        if (!gid && pos == TA - 1) {
#pragma unroll
            for (int nj = 0; nj < 16; nj++)
#pragma unroll
                for (int c = 0; c < 4; c++) {
                    int row = wg * 16 + g + (c >> 1) * 8;
                    int col = nj * 8 + 2 * tg + (c & 1);
                    stg[row * 133 + col] = acc[nj][c];
                }
            barg(1);
            {
                int qq = gtid & 63, db = gtid >> 6;
                const float* xin = mb + (size_t)b * ND * NT;
                float* o = out + (size_t)b * ND * NT;
#pragma unroll
                for (int i = 0; i < 64; i++) {
                    int d_ = db + i * 2;
                    o[d_ * NT + q0A + qq] = xin[d_ * NT + q0A + qq] + stg[qq * 133 + d_];
                }
            }
            barg(1);
#pragma unroll
            for (int nj = 0; nj < 16; nj++)
#pragma unroll
                for (int c = 0; c < 4; c++) acc[nj][c] = 0.0f;
#pragma unroll
            for (int kk2 = 0; kk2 < 4; kk2++)
                ldsm4(qa_[kk2], sb + 9216 + ((wg * 16 + arow) * 72 + kk2 * 16 + acol) * 2);
            myqt = qtB;
        }

        barg(mybar);
        buf ^= 1;
    }

    // combine: gid0's tile-B partial -> gid1
    if (!gid) {
#pragma unroll
        for (int nj = 0; nj < 16; nj++)
#pragma unroll
            for (int c = 0; c < 4; c++)
                stg[gtid * 64 + nj * 4 + c] = acc[nj][c];
    }
    __syncthreads();
    if (gid) {
#pragma unroll
        for (int nj = 0; nj < 16; nj++)
#pragma unroll
            for (int c = 0; c < 4; c++)
                acc[nj][c] += stg[gtid * 64 + nj * 4 + c];
        barg(2);
#pragma unroll
        for (int nj = 0; nj < 16; nj++)
#pragma unroll
            for (int c = 0; c < 4; c++) {
                int row = wg * 16 + g + (c >> 1) * 8;
                int col = nj * 8 + 2 * tg + (c & 1);
                stg[row * 133 + col] = acc[nj][c];
            }
        barg(2);
        {
            int qq = gtid & 63, db = gtid >> 6;
            const float* xin = mb + (size_t)b * ND * NT;
            float* o = out + (size_t)b * ND * NT;
#pragma unroll
            for (int i = 0; i < 64; i++) {
                int d_ = db + i * 2;
                o[d_ * NT + q0B + qq] = xin[d_ * NT + q0B + qq] + stg[qq * 133 + d_];
            }
        }
    }
}

// ---------------------------------------------------------------------------
extern "C" void kernel_launch(void* const* d_in, const int* in_sizes, int n_in,
                              void* d_out, int out_size) {
    const float* mb = (const float*)d_in[0];
    const float* Wk = (const float*)d_in[1];
    const float* bk = (const float*)d_in[2];
    const float* Wq = (const float*)d_in[3];
    const float* bq = (const float*)d_in[4];
    const float* Wv = (const float*)d_in[5];
    const float* bv = (const float*)d_in[6];
    float* out = (float*)d_out;

    cudaFuncSetAttribute(attn_kernel, cudaFuncAttributeMaxDynamicSharedMemorySize, ATT_SMEM);

    prep_kernel<<<64, 256>>>(Wk, bk, Wq, bq, Wv, bv);
    qkv_kernel<<<dim3(4, 256), 256>>>(mb);
    colsum_kernel<<<dim3(64, 4, 8), 256>>>();
    inv_kernel<<<(NB * NT) / 256, 256>>>();
    attn_kernel<<<dim3(32, 4), 256, ATT_SMEM>>>(mb, out);
}

// round 11
// speedup vs baseline: 1.2480x; 1.1148x over previous
#include <cuda_runtime.h>
#include <cuda_bf16.h>
#include <math.h>

#define NB 4
#define ND 128
#define NT 4096

__device__ __nv_bfloat16 g_QKb[NB * NT * 128];  // per row: [Q(64)|K(64)] bf16
__device__ __nv_bfloat16 g_Vb[NB * NT * 128];   // V bf16
__device__ float g_colsum[NB * NT];
__device__ float g_inv[NB * NT];                // 1/(8*colsum)
__device__ int   g_cnt[NB * 64];                // per t-tile completion counters

// ---------------------------------------------------------------------------
__device__ __forceinline__ void mma8(float* d, const unsigned* a, const unsigned* b) {
    asm volatile(
        "mma.sync.aligned.m16n8k8.row.col.f32.tf32.tf32.f32 "
        "{%0,%1,%2,%3}, {%4,%5,%6,%7}, {%8,%9}, {%0,%1,%2,%3};\n"
        : "+f"(d[0]), "+f"(d[1]), "+f"(d[2]), "+f"(d[3])
        : "r"(a[0]), "r"(a[1]), "r"(a[2]), "r"(a[3]), "r"(b[0]), "r"(b[1]));
}
__device__ __forceinline__ void mma16(float* d, const unsigned* a, const unsigned* b) {
    asm volatile(
        "mma.sync.aligned.m16n8k16.row.col.f32.bf16.bf16.f32 "
        "{%0,%1,%2,%3}, {%4,%5,%6,%7}, {%8,%9}, {%0,%1,%2,%3};\n"
        : "+f"(d[0]), "+f"(d[1]), "+f"(d[2]), "+f"(d[3])
        : "r"(a[0]), "r"(a[1]), "r"(a[2]), "r"(a[3]), "r"(b[0]), "r"(b[1]));
}
__device__ __forceinline__ unsigned packbf(float lo, float hi) {
    unsigned r;
    asm("cvt.rn.bf16x2.f32 %0, %1, %2;" : "=r"(r) : "f"(hi), "f"(lo));
    return r;
}
__device__ __forceinline__ void ldsm4(unsigned* r, unsigned addr) {
    asm volatile("ldmatrix.sync.aligned.m8n8.x4.shared.b16 {%0,%1,%2,%3}, [%4];"
                 : "=r"(r[0]), "=r"(r[1]), "=r"(r[2]), "=r"(r[3]) : "r"(addr));
}
__device__ __forceinline__ void ldsm4t(unsigned* r, unsigned addr) {
    asm volatile("ldmatrix.sync.aligned.m8n8.x4.trans.shared.b16 {%0,%1,%2,%3}, [%4];"
                 : "=r"(r[0]), "=r"(r[1]), "=r"(r[2]), "=r"(r[3]) : "r"(addr));
}
__device__ __forceinline__ void cpa16(unsigned saddr, const void* gsrc) {
    asm volatile("cp.async.cg.shared.global [%0], [%1], 16;" :: "r"(saddr), "l"(gsrc));
}
__device__ __forceinline__ void cpcommit() { asm volatile("cp.async.commit_group;"); }
template <int N>
__device__ __forceinline__ void cpwait() { asm volatile("cp.async.wait_group %0;" :: "n"(N)); }
__device__ __forceinline__ unsigned fas(float x) { return __float_as_uint(x); }
__device__ __forceinline__ unsigned ldu32(const __nv_bfloat16* p) { return *(const unsigned*)p; }

// ---------------------------------------------------------------------------
// QKV via tf32 mma, reading raw weights. Also zeroes colsum/counters (n0==0 blocks).
__global__ __launch_bounds__(256) void qkv_kernel(const float* __restrict__ mb,
                                                  const float* __restrict__ Wq,
                                                  const float* __restrict__ bq,
                                                  const float* __restrict__ Wk,
                                                  const float* __restrict__ bk,
                                                  const float* __restrict__ Wv,
                                                  const float* __restrict__ bv) {
    __shared__ float Xs[64 * 68];
    __shared__ float Ws[64 * 68];
    int n0 = blockIdx.x * 64, m0 = blockIdx.y * 64;
    int b = m0 >> 12, t0 = m0 & (NT - 1);
    const float* x = mb + (size_t)b * ND * NT;
    int tid = threadIdx.x, lane = tid & 31, w = tid >> 5;
    int g = lane >> 2, tg = lane & 3;
    int wr = w & 3, wc = w >> 2;

    // weight/bias source select for this n-tile
    const float* Wsrc;
    const float* bsrc;
    int nr0, boff;
    if (n0 == 0)        { Wsrc = Wq; nr0 = 0;  bsrc = bq; boff = 0;   }
    else if (n0 == 64)  { Wsrc = Wk; nr0 = 0;  bsrc = bk; boff = 64;  }
    else if (n0 == 128) { Wsrc = Wv; nr0 = 0;  bsrc = bv; boff = 128; }
    else                { Wsrc = Wv; nr0 = 64; bsrc = bv; boff = 128; }

    if (blockIdx.x == 0) {          // zero colsum + counter for this m-tile
        if (tid < 64) g_colsum[m0 + tid] = 0.0f;
        if (tid == 64) g_cnt[blockIdx.y] = 0;
    }

    float acc[4][4] = {};
    for (int k0 = 0; k0 < 128; k0 += 64) {
        __syncthreads();
#pragma unroll
        for (int i = 0; i < 16; i++) {
            int idx = tid + 256 * i;
            int r = idx & 63, d = idx >> 6;
            Xs[r * 68 + d] = x[(k0 + d) * NT + t0 + r];
        }
#pragma unroll
        for (int i = 0; i < 16; i++) {
            int idx = tid + 256 * i;
            int dd = idx & 63, n = idx >> 6;
            Ws[n * 68 + dd] = Wsrc[(nr0 + n) * 128 + k0 + dd];
        }
        __syncthreads();
#pragma unroll
        for (int kk = 0; kk < 8; kk++) {
            unsigned a[4];
            a[0] = fas(Xs[(wr * 16 + g) * 68 + kk * 8 + tg]);
            a[1] = fas(Xs[(wr * 16 + g + 8) * 68 + kk * 8 + tg]);
            a[2] = fas(Xs[(wr * 16 + g) * 68 + kk * 8 + tg + 4]);
            a[3] = fas(Xs[(wr * 16 + g + 8) * 68 + kk * 8 + tg + 4]);
#pragma unroll
            for (int ni = 0; ni < 4; ni++) {
                unsigned b2[2];
                b2[0] = fas(Ws[(wc * 32 + ni * 8 + g) * 68 + kk * 8 + tg]);
                b2[1] = fas(Ws[(wc * 32 + ni * 8 + g) * 68 + kk * 8 + tg + 4]);
                mma8(acc[ni], a, b2);
            }
        }
    }
#pragma unroll
    for (int ni = 0; ni < 4; ni++) {
        int n = n0 + wc * 32 + ni * 8 + 2 * tg;
        float b0 = bsrc[n - boff], b1 = bsrc[n + 1 - boff];
        int r1 = m0 + wr * 16 + g, r2 = r1 + 8;
        if (n0 < 128) {
            *(unsigned*)&g_QKb[(size_t)r1 * 128 + n] = packbf(acc[ni][0] + b0, acc[ni][1] + b1);
            *(unsigned*)&g_QKb[(size_t)r2 * 128 + n] = packbf(acc[ni][2] + b0, acc[ni][3] + b1);
        } else {
            *(unsigned*)&g_Vb[(size_t)r1 * 128 + n - 128] = packbf(acc[ni][0] + b0, acc[ni][1] + b1);
            *(unsigned*)&g_Vb[(size_t)r2 * 128 + n - 128] = packbf(acc[ni][2] + b0, acc[ni][3] + b1);
        }
    }
}

// ---------------------------------------------------------------------------
// colsum[b][t] = sum_{q>=t} exp(Q[q].K[t]); LAST contributing block computes g_inv.
__global__ __launch_bounds__(256) void colsum_kernel() {
    const int QCHUNK = 512;
    int t0 = blockIdx.x * 64, b = blockIdx.y, qlo = blockIdx.z * QCHUNK;
    if (qlo + QCHUNK - 1 < t0) return;
    __shared__ __align__(16) __nv_bfloat16 Ksm[64 * 72];
    __shared__ __align__(16) __nv_bfloat16 Qsm[2][64 * 72];
    __shared__ float cs[64];
    __shared__ int is_last;
    const __nv_bfloat16* qk = g_QKb + (size_t)b * NT * 128;
    int tid = threadIdx.x, lane = tid & 31, w = tid >> 5;
    int g = lane >> 2, tg = lane & 3, wr = w & 1, wc = w >> 1;
    unsigned sbq = (unsigned)__cvta_generic_to_shared(&Qsm[0][0]);

    { int c = tid & 7, r0 = tid >> 3;
#pragma unroll
      for (int i = 0; i < 2; i++) { int r = r0 + 32 * i;
          *(uint4*)&Ksm[r * 72 + c * 8] = *(const uint4*)&qk[(size_t)(t0 + r) * 128 + 64 + c * 8]; } }
    if (tid < 64) cs[tid] = 0.0f;
    { int c = tid & 7, r0 = tid >> 3;
#pragma unroll
      for (int i = 0; i < 2; i++) { int r = r0 + 32 * i;
          cpa16(sbq + (r * 72 + c * 8) * 2, qk + (size_t)(qlo + r) * 128 + c * 8); } }
    cpcommit();
    __syncthreads();

    unsigned bf[2][4][2];
#pragma unroll
    for (int ni = 0; ni < 2; ni++)
#pragma unroll
        for (int kk2 = 0; kk2 < 4; kk2++) {
            int n = wc * 16 + ni * 8 + g;
            bf[ni][kk2][0] = ldu32(&Ksm[n * 72 + kk2 * 16 + 2 * tg]);
            bf[ni][kk2][1] = ldu32(&Ksm[n * 72 + kk2 * 16 + 8 + 2 * tg]);
        }

    float colacc[2][2] = {};
    int buf = 0;
    int arow = (lane & 7) + ((lane >> 3) & 1) * 8;
    int acol = (lane >> 4) * 8;
    for (int q0 = qlo; q0 < qlo + QCHUNK; q0 += 64) {
        if (q0 + 64 < qlo + QCHUNK) {
            int c = tid & 7, r0 = tid >> 3, bo = buf ^ 1;
#pragma unroll
            for (int i = 0; i < 2; i++) { int r = r0 + 32 * i;
                cpa16(sbq + bo * 9216 + (r * 72 + c * 8) * 2,
                      qk + (size_t)(q0 + 64 + r) * 128 + c * 8); }
        }
        cpcommit(); cpwait<1>(); __syncthreads();
        if (q0 + 63 >= t0) {
            unsigned qbase = sbq + buf * 9216;
            float d[2][2][4] = {};
#pragma unroll
            for (int kk2 = 0; kk2 < 4; kk2++) {
                unsigned a[2][4];
#pragma unroll
                for (int mi = 0; mi < 2; mi++) {
                    int r = wr * 32 + mi * 16 + arow;
                    ldsm4(a[mi], qbase + (r * 72 + kk2 * 16 + acol) * 2);
                }
#pragma unroll
                for (int mi = 0; mi < 2; mi++)
#pragma unroll
                    for (int ni = 0; ni < 2; ni++)
                        mma16(d[mi][ni], a[mi], bf[ni][kk2]);
            }
#pragma unroll
            for (int mi = 0; mi < 2; mi++)
#pragma unroll
                for (int ni = 0; ni < 2; ni++)
#pragma unroll
                    for (int e = 0; e < 4; e++) {
                        int row = q0 + wr * 32 + mi * 16 + g + (e >> 1) * 8;
                        int col = t0 + wc * 16 + ni * 8 + 2 * tg + (e & 1);
                        if (row >= col) colacc[ni][e & 1] += __expf(d[mi][ni][e]);
                    }
        }
        __syncthreads();
        buf ^= 1;
    }
#pragma unroll
    for (int ni = 0; ni < 2; ni++)
#pragma unroll
        for (int j = 0; j < 2; j++) {
            float v = colacc[ni][j];
            v += __shfl_xor_sync(0xffffffffu, v, 4);
            v += __shfl_xor_sync(0xffffffffu, v, 8);
            v += __shfl_xor_sync(0xffffffffu, v, 16);
            colacc[ni][j] = v;
        }
    if (g == 0)
#pragma unroll
        for (int ni = 0; ni < 2; ni++) {
            atomicAdd(&cs[wc * 16 + ni * 8 + 2 * tg], colacc[ni][0]);
            atomicAdd(&cs[wc * 16 + ni * 8 + 2 * tg + 1], colacc[ni][1]);
        }
    __syncthreads();
    if (tid < 64) atomicAdd(&g_colsum[b * NT + t0 + tid], cs[tid]);

    // last-contributor detection -> compute g_inv for this t-tile
    __threadfence();
    __syncthreads();
    if (tid == 0) {
        int n_contrib = 8 - (t0 >> 9);
        int old = atomicAdd(&g_cnt[b * 64 + (t0 >> 6)], 1);
        is_last = (old == n_contrib - 1);
    }
    __syncthreads();
    if (is_last && tid < 64) {
        __threadfence();
        float v = __ldcg(&g_colsum[b * NT + t0 + tid]);
        g_inv[b * NT + t0 + tid] = 1.0f / (8.0f * v);
    }
}

// ---------------------------------------------------------------------------
// attn (R7 structure): block xx handles q-tiles (xx, 63-xx). Warps 0-3 tile A, 4-7 tile B.
#define AT_KB 18432
#define AT_VB 36864
#define AT_IB 71680
#define ATT_SMEM 72192

__global__ __launch_bounds__(256, 1) void attn_kernel(const float* __restrict__ mb,
                                                      float* __restrict__ out) {
    extern __shared__ float sm[];
    __nv_bfloat16* smb = (__nv_bfloat16*)sm;
    float* invs = (float*)((char*)sm + AT_IB);
    int xx = blockIdx.x, b = blockIdx.y;
    int qtA = xx, qtB = 63 - xx;
    int q0A = qtA * 64, q0B = qtB * 64;
    const __nv_bfloat16* qk = g_QKb + (size_t)b * NT * 128;
    const __nv_bfloat16* vsb = g_Vb + (size_t)b * NT * 128;
    const float* invp = g_inv + (size_t)b * NT;
    int tid = threadIdx.x, lane = tid & 31, w = tid >> 5;
    int g = lane >> 2, tg = lane & 3;
    int gid = w >> 2, wg = w & 3;
    int myqt = gid ? qtB : qtA;
    unsigned sb = (unsigned)__cvta_generic_to_shared(sm);

#pragma unroll
    for (int i = 0; i < 4; i++) {
        int idx = tid + 256 * i;
        int grp = idx >> 9, rem = idx & 511, r = rem >> 3, c = rem & 7;
        int q0g = grp ? q0B : q0A;
        *(uint4*)&smb[grp * 4608 + r * 72 + c * 8] =
            *(const uint4*)&qk[(size_t)(q0g + r) * 128 + c * 8];
    }
#pragma unroll
    for (int i = 0; i < 2; i++) { int idx = tid + 256 * i; int r = idx >> 3, c = idx & 7;
        cpa16(sb + AT_KB + (r * 72 + c * 8) * 2, qk + (size_t)r * 128 + 64 + c * 8); }
#pragma unroll
    for (int i = 0; i < 4; i++) { int idx = tid + 256 * i; int r = idx >> 4, c = idx & 15;
        cpa16(sb + AT_VB + (r * 136 + c * 8) * 2, vsb + (size_t)r * 128 + c * 8); }
    if (tid < 16) cpa16(sb + AT_IB + tid * 16, invp + tid * 4);
    cpcommit();
    __syncthreads();

    int arow = (lane & 7) + ((lane >> 3) & 1) * 8;
    int acol = (lane >> 4) * 8;
    unsigned qbase = sb + gid * 9216;
    unsigned qa_[4][4];
#pragma unroll
    for (int kk2 = 0; kk2 < 4; kk2++)
        ldsm4(qa_[kk2], qbase + ((wg * 16 + arow) * 72 + kk2 * 16 + acol) * 2);

    int krow = ((lane >> 4) << 3) + (lane & 7);
    int kcol = ((lane >> 3) & 1) * 8;

    float acc[16][4] = {};
    int buf = 0;
    int sub = lane >> 3, li = lane & 7;
    for (int tt = 0; tt <= qtB; tt++) {
        if (tt < qtB) {
            int t1 = (tt + 1) * 64, bo = buf ^ 1;
#pragma unroll
            for (int i = 0; i < 2; i++) { int idx = tid + 256 * i; int r = idx >> 3, c = idx & 7;
                cpa16(sb + AT_KB + bo * 9216 + (r * 72 + c * 8) * 2,
                      qk + (size_t)(t1 + r) * 128 + 64 + c * 8); }
#pragma unroll
            for (int i = 0; i < 4; i++) { int idx = tid + 256 * i; int r = idx >> 4, c = idx & 15;
                cpa16(sb + AT_VB + bo * 17408 + (r * 136 + c * 8) * 2,
                      vsb + (size_t)(t1 + r) * 128 + c * 8); }
            if (tid < 16) cpa16(sb + AT_IB + bo * 256 + tid * 16, invp + t1 + tid * 4);
        }
        cpcommit(); cpwait<1>(); __syncthreads();

        if (tt <= myqt) {
            unsigned kbase = sb + AT_KB + buf * 9216;
            float d[8][4] = {};
#pragma unroll
            for (int kk2 = 0; kk2 < 4; kk2++)
#pragma unroll
                for (int nb = 0; nb < 4; nb++) {
                    unsigned r4[4];
                    ldsm4(r4, kbase + ((nb * 16 + krow) * 72 + kk2 * 16 + kcol) * 2);
                    mma16(d[nb * 2 + 0], qa_[kk2], &r4[0]);
                    mma16(d[nb * 2 + 1], qa_[kk2], &r4[2]);
                }
            bool diag = (tt == myqt);
            const float* ivt = invs + buf * 64;
            unsigned Af[4][4];
#pragma unroll
            for (int ni = 0; ni < 8; ni++) {
                float2 iv = *(const float2*)&ivt[ni * 8 + 2 * tg];
                float e[4];
#pragma unroll
                for (int c = 0; c < 4; c++) {
                    int row = wg * 16 + g + (c >> 1) * 8;
                    int col = ni * 8 + 2 * tg + (c & 1);
                    float v = __expf(d[ni][c]) * ((c & 1) ? iv.y : iv.x);
                    e[c] = (diag && col > row) ? 0.0f : v;
                }
                Af[ni >> 1][(ni & 1) * 2 + 0] = packbf(e[0], e[1]);
                Af[ni >> 1][(ni & 1) * 2 + 1] = packbf(e[2], e[3]);
            }
#pragma unroll
            for (int kc = 0; kc < 4; kc++)
#pragma unroll
                for (int nj = 0; nj < 8; nj++) {
                    unsigned r4[4];
                    unsigned addr = sb + AT_VB + buf * 17408 +
                        ((kc * 16 + (sub & 1) * 8 + li) * 136 + nj * 16 + (sub >> 1) * 8) * 2;
                    ldsm4t(r4, addr);
                    mma16(acc[nj * 2 + 0], Af[kc], &r4[0]);
                    mma16(acc[nj * 2 + 1], Af[kc], &r4[2]);
                }
        }
        __syncthreads();
        buf ^= 1;
    }

    float* stg = gid ? (sm + 8704) : sm;
#pragma unroll
    for (int nj = 0; nj < 16; nj++)
#pragma unroll
        for (int c = 0; c < 4; c++) {
            int row = wg * 16 + g + (c >> 1) * 8;
            int col = nj * 8 + 2 * tg + (c & 1);
            stg[row * 133 + col] = acc[nj][c];
        }
    __syncthreads();
    {
        int gw = tid >> 7, gtid = tid & 127;
        int qq = gtid & 63, db = gtid >> 6;
        const float* s2 = gw ? (sm + 8704) : sm;
        int q0w = gw ? q0B : q0A;
        const float* xin = mb + (size_t)b * ND * NT;
        float* o = out + (size_t)b * ND * NT;
#pragma unroll
        for (int i = 0; i < 64; i++) {
            int d_ = db + i * 2;
            o[d_ * NT + q0w + qq] = xin[d_ * NT + q0w + qq] + s2[qq * 133 + d_];
        }
    }
}

// ---------------------------------------------------------------------------
extern "C" void kernel_launch(void* const* d_in, const int* in_sizes, int n_in,
                              void* d_out, int out_size) {
    const float* mb = (const float*)d_in[0];
    const float* Wk = (const float*)d_in[1];
    const float* bk = (const float*)d_in[2];
    const float* Wq = (const float*)d_in[3];
    const float* bq = (const float*)d_in[4];
    const float* Wv = (const float*)d_in[5];
    const float* bv = (const float*)d_in[6];
    float* out = (float*)d_out;

    cudaFuncSetAttribute(attn_kernel, cudaFuncAttributeMaxDynamicSharedMemorySize, ATT_SMEM);

    qkv_kernel<<<dim3(4, 256), 256>>>(mb, Wq, bq, Wk, bk, Wv, bv);
    colsum_kernel<<<dim3(64, 4, 8), 256>>>();
    attn_kernel<<<dim3(32, 4), 256, ATT_SMEM>>>(mb, out);
}

// round 12
// speedup vs baseline: 1.3462x; 1.0787x over previous
#include <cuda_runtime.h>
#include <cuda_bf16.h>
#include <math.h>

#define NB 4
#define ND 128
#define NT 4096
#define LOG2E 1.4426950408889634f

__device__ __nv_bfloat16 g_QKb[NB * NT * 128];  // per row: [Q(64)*log2e | K(64)] bf16
__device__ __nv_bfloat16 g_Vb[NB * NT * 128];   // V bf16
__device__ float g_colsum[NB * NT];
__device__ float g_inv[NB * NT];                // 1/(8*colsum)
__device__ int   g_cnt[NB * 64];                // per t-tile completion counters

// ---------------------------------------------------------------------------
__device__ __forceinline__ void mma16(float* d, const unsigned* a, const unsigned* b) {
    asm volatile(
        "mma.sync.aligned.m16n8k16.row.col.f32.bf16.bf16.f32 "
        "{%0,%1,%2,%3}, {%4,%5,%6,%7}, {%8,%9}, {%0,%1,%2,%3};\n"
        : "+f"(d[0]), "+f"(d[1]), "+f"(d[2]), "+f"(d[3])
        : "r"(a[0]), "r"(a[1]), "r"(a[2]), "r"(a[3]), "r"(b[0]), "r"(b[1]));
}
__device__ __forceinline__ unsigned packbf(float lo, float hi) {
    unsigned r;
    asm("cvt.rn.bf16x2.f32 %0, %1, %2;" : "=r"(r) : "f"(hi), "f"(lo));
    return r;
}
__device__ __forceinline__ void ldsm4(unsigned* r, unsigned addr) {
    asm volatile("ldmatrix.sync.aligned.m8n8.x4.shared.b16 {%0,%1,%2,%3}, [%4];"
                 : "=r"(r[0]), "=r"(r[1]), "=r"(r[2]), "=r"(r[3]) : "r"(addr));
}
__device__ __forceinline__ void ldsm4t(unsigned* r, unsigned addr) {
    asm volatile("ldmatrix.sync.aligned.m8n8.x4.trans.shared.b16 {%0,%1,%2,%3}, [%4];"
                 : "=r"(r[0]), "=r"(r[1]), "=r"(r[2]), "=r"(r[3]) : "r"(addr));
}
__device__ __forceinline__ void cpa16(unsigned saddr, const void* gsrc) {
    asm volatile("cp.async.cg.shared.global [%0], [%1], 16;" :: "r"(saddr), "l"(gsrc));
}
__device__ __forceinline__ void cpcommit() { asm volatile("cp.async.commit_group;"); }
template <int N>
__device__ __forceinline__ void cpwait() { asm volatile("cp.async.wait_group %0;" :: "n"(N)); }
__device__ __forceinline__ unsigned ldu32(const __nv_bfloat16* p) { return *(const unsigned*)p; }

// ---------------------------------------------------------------------------
// QKV via bf16 mma16 + ldmatrix. Also zeroes colsum/counters (n0==0 blocks).
// Q output pre-scaled by log2e (attn/colsum use exp2).
__global__ __launch_bounds__(256) void qkv_kernel(const float* __restrict__ mb,
                                                  const float* __restrict__ Wq,
                                                  const float* __restrict__ bq,
                                                  const float* __restrict__ Wk,
                                                  const float* __restrict__ bk,
                                                  const float* __restrict__ Wv,
                                                  const float* __restrict__ bv) {
    __shared__ __align__(16) __nv_bfloat16 Xb[64 * 136];
    __shared__ __align__(16) __nv_bfloat16 Wb[64 * 136];
    int n0 = blockIdx.x * 64, m0 = blockIdx.y * 64;
    int b = m0 >> 12, t0 = m0 & (NT - 1);
    const float* x = mb + (size_t)b * ND * NT;
    int tid = threadIdx.x, lane = tid & 31, w = tid >> 5;
    int g = lane >> 2, tg = lane & 3;
    int wr = w & 3, wc = w >> 2;

    const float* Wsrc; const float* bsrc; int nr0, boff;
    if (n0 == 0)        { Wsrc = Wq; nr0 = 0;  bsrc = bq; boff = 0;   }
    else if (n0 == 64)  { Wsrc = Wk; nr0 = 0;  bsrc = bk; boff = 64;  }
    else if (n0 == 128) { Wsrc = Wv; nr0 = 0;  bsrc = bv; boff = 128; }
    else                { Wsrc = Wv; nr0 = 64; bsrc = bv; boff = 128; }

    if (blockIdx.x == 0) {
        if (tid < 64) g_colsum[m0 + tid] = 0.0f;
        if (tid == 64) g_cnt[blockIdx.y] = 0;
    }

    // X: [t-row r][d] bf16, packed pairs along d. Global loads coalesced over r.
#pragma unroll
    for (int i = 0; i < 16; i++) {
        int idx = tid + 256 * i;                 // 0..4095
        int r = idx & 63, d2 = idx >> 6;         // d2 0..63
        float v0 = x[(2 * d2) * NT + t0 + r];
        float v1 = x[(2 * d2 + 1) * NT + t0 + r];
        *(unsigned*)&Xb[r * 136 + 2 * d2] = packbf(v0, v1);
    }
    // W: [n][d] bf16; global float2 coalesced over d2; conflict-free row stores.
#pragma unroll
    for (int i = 0; i < 16; i++) {
        int idx = tid + 256 * i;
        int d2 = idx & 63, n = idx >> 6;
        float2 wv = *(const float2*)&Wsrc[(nr0 + n) * 128 + 2 * d2];
        *(unsigned*)&Wb[n * 136 + 2 * d2] = packbf(wv.x, wv.y);
    }
    __syncthreads();

    int arow = (lane & 7) + ((lane >> 3) & 1) * 8;
    int acol = (lane >> 4) * 8;
    int krow = ((lane >> 4) << 3) + (lane & 7);
    int kcol = ((lane >> 3) & 1) * 8;
    unsigned xb = (unsigned)__cvta_generic_to_shared(Xb);
    unsigned wb = (unsigned)__cvta_generic_to_shared(Wb);

    float acc[4][4] = {};
#pragma unroll
    for (int kk2 = 0; kk2 < 8; kk2++) {
        unsigned a[4];
        ldsm4(a, xb + ((wr * 16 + arow) * 136 + kk2 * 16 + acol) * 2);
#pragma unroll
        for (int nb = 0; nb < 2; nb++) {
            unsigned r4[4];
            ldsm4(r4, wb + ((wc * 32 + nb * 16 + krow) * 136 + kk2 * 16 + kcol) * 2);
            mma16(acc[nb * 2 + 0], a, &r4[0]);
            mma16(acc[nb * 2 + 1], a, &r4[2]);
        }
    }

    float qs = (n0 == 0) ? LOG2E : 1.0f;
#pragma unroll
    for (int ni = 0; ni < 4; ni++) {
        int n = n0 + wc * 32 + ni * 8 + 2 * tg;
        float b0 = bsrc[n - boff], b1 = bsrc[n + 1 - boff];
        int r1 = m0 + wr * 16 + g, r2 = r1 + 8;
        if (n0 < 128) {
            *(unsigned*)&g_QKb[(size_t)r1 * 128 + n] =
                packbf((acc[ni][0] + b0) * qs, (acc[ni][1] + b1) * qs);
            *(unsigned*)&g_QKb[(size_t)r2 * 128 + n] =
                packbf((acc[ni][2] + b0) * qs, (acc[ni][3] + b1) * qs);
        } else {
            *(unsigned*)&g_Vb[(size_t)r1 * 128 + n - 128] = packbf(acc[ni][0] + b0, acc[ni][1] + b1);
            *(unsigned*)&g_Vb[(size_t)r2 * 128 + n - 128] = packbf(acc[ni][2] + b0, acc[ni][3] + b1);
        }
    }
}

// ---------------------------------------------------------------------------
// colsum[b][t] = sum_{q>=t} exp2(Q'[q].K[t]); LAST contributing block computes g_inv.
__global__ __launch_bounds__(256) void colsum_kernel() {
    const int QCHUNK = 512;
    int t0 = blockIdx.x * 64, b = blockIdx.y, qlo = blockIdx.z * QCHUNK;
    if (qlo + QCHUNK - 1 < t0) return;
    __shared__ __align__(16) __nv_bfloat16 Ksm[64 * 72];
    __shared__ __align__(16) __nv_bfloat16 Qsm[2][64 * 72];
    __shared__ float cs[64];
    __shared__ int is_last;
    const __nv_bfloat16* qk = g_QKb + (size_t)b * NT * 128;
    int tid = threadIdx.x, lane = tid & 31, w = tid >> 5;
    int g = lane >> 2, tg = lane & 3, wr = w & 1, wc = w >> 1;
    unsigned sbq = (unsigned)__cvta_generic_to_shared(&Qsm[0][0]);

    { int c = tid & 7, r0 = tid >> 3;
#pragma unroll
      for (int i = 0; i < 2; i++) { int r = r0 + 32 * i;
          *(uint4*)&Ksm[r * 72 + c * 8] = *(const uint4*)&qk[(size_t)(t0 + r) * 128 + 64 + c * 8]; } }
    if (tid < 64) cs[tid] = 0.0f;
    { int c = tid & 7, r0 = tid >> 3;
#pragma unroll
      for (int i = 0; i < 2; i++) { int r = r0 + 32 * i;
          cpa16(sbq + (r * 72 + c * 8) * 2, qk + (size_t)(qlo + r) * 128 + c * 8); } }
    cpcommit();
    __syncthreads();

    unsigned bf[2][4][2];
#pragma unroll
    for (int ni = 0; ni < 2; ni++)
#pragma unroll
        for (int kk2 = 0; kk2 < 4; kk2++) {
            int n = wc * 16 + ni * 8 + g;
            bf[ni][kk2][0] = ldu32(&Ksm[n * 72 + kk2 * 16 + 2 * tg]);
            bf[ni][kk2][1] = ldu32(&Ksm[n * 72 + kk2 * 16 + 8 + 2 * tg]);
        }

    float colacc[2][2] = {};
    int buf = 0;
    int arow = (lane & 7) + ((lane >> 3) & 1) * 8;
    int acol = (lane >> 4) * 8;
    for (int q0 = qlo; q0 < qlo + QCHUNK; q0 += 64) {
        if (q0 + 64 < qlo + QCHUNK) {
            int c = tid & 7, r0 = tid >> 3, bo = buf ^ 1;
#pragma unroll
            for (int i = 0; i < 2; i++) { int r = r0 + 32 * i;
                cpa16(sbq + bo * 9216 + (r * 72 + c * 8) * 2,
                      qk + (size_t)(q0 + 64 + r) * 128 + c * 8); }
        }
        cpcommit(); cpwait<1>(); __syncthreads();
        if (q0 + 63 >= t0) {
            unsigned qbase = sbq + buf * 9216;
            float d[2][2][4] = {};
#pragma unroll
            for (int kk2 = 0; kk2 < 4; kk2++) {
                unsigned a[2][4];
#pragma unroll
                for (int mi = 0; mi < 2; mi++) {
                    int r = wr * 32 + mi * 16 + arow;
                    ldsm4(a[mi], qbase + (r * 72 + kk2 * 16 + acol) * 2);
                }
#pragma unroll
                for (int mi = 0; mi < 2; mi++)
#pragma unroll
                    for (int ni = 0; ni < 2; ni++)
                        mma16(d[mi][ni], a[mi], bf[ni][kk2]);
            }
#pragma unroll
            for (int mi = 0; mi < 2; mi++)
#pragma unroll
                for (int ni = 0; ni < 2; ni++)
#pragma unroll
                    for (int e = 0; e < 4; e++) {
                        int row = q0 + wr * 32 + mi * 16 + g + (e >> 1) * 8;
                        int col = t0 + wc * 16 + ni * 8 + 2 * tg + (e & 1);
                        if (row >= col) colacc[ni][e & 1] += exp2f(d[mi][ni][e]);
                    }
        }
        __syncthreads();
        buf ^= 1;
    }
#pragma unroll
    for (int ni = 0; ni < 2; ni++)
#pragma unroll
        for (int j = 0; j < 2; j++) {
            float v = colacc[ni][j];
            v += __shfl_xor_sync(0xffffffffu, v, 4);
            v += __shfl_xor_sync(0xffffffffu, v, 8);
            v += __shfl_xor_sync(0xffffffffu, v, 16);
            colacc[ni][j] = v;
        }
    if (g == 0)
#pragma unroll
        for (int ni = 0; ni < 2; ni++) {
            atomicAdd(&cs[wc * 16 + ni * 8 + 2 * tg], colacc[ni][0]);
            atomicAdd(&cs[wc * 16 + ni * 8 + 2 * tg + 1], colacc[ni][1]);
        }
    __syncthreads();
    if (tid < 64) atomicAdd(&g_colsum[b * NT + t0 + tid], cs[tid]);

    __threadfence();
    __syncthreads();
    if (tid == 0) {
        int n_contrib = 8 - (t0 >> 9);
        int old = atomicAdd(&g_cnt[b * 64 + (t0 >> 6)], 1);
        is_last = (old == n_contrib - 1);
    }
    __syncthreads();
    if (is_last && tid < 64) {
        __threadfence();
        float v = __ldcg(&g_colsum[b * NT + t0 + tid]);
        g_inv[b * NT + t0 + tid] = 1.0f / (8.0f * v);
    }
}

// ---------------------------------------------------------------------------
// attn: block xx handles q-tiles (xx, 63-xx). Warps 0-3 tile A, 4-7 tile B.
#define AT_KB 18432
#define AT_VB 36864
#define AT_IB 71680
#define ATT_SMEM 72192

__global__ __launch_bounds__(256, 1) void attn_kernel(const float* __restrict__ mb,
                                                      float* __restrict__ out) {
    extern __shared__ float sm[];
    __nv_bfloat16* smb = (__nv_bfloat16*)sm;
    float* invs = (float*)((char*)sm + AT_IB);
    int xx = blockIdx.x, b = blockIdx.y;
    int qtA = xx, qtB = 63 - xx;
    int q0A = qtA * 64, q0B = qtB * 64;
    const __nv_bfloat16* qk = g_QKb + (size_t)b * NT * 128;
    const __nv_bfloat16* vsb = g_Vb + (size_t)b * NT * 128;
    const float* invp = g_inv + (size_t)b * NT;
    int tid = threadIdx.x, lane = tid & 31, w = tid >> 5;
    int g = lane >> 2, tg = lane & 3;
    int gid = w >> 2, wg = w & 3;
    int myqt = gid ? qtB : qtA;
    unsigned sb = (unsigned)__cvta_generic_to_shared(sm);

#pragma unroll
    for (int i = 0; i < 4; i++) {
        int idx = tid + 256 * i;
        int grp = idx >> 9, rem = idx & 511, r = rem >> 3, c = rem & 7;
        int q0g = grp ? q0B : q0A;
        *(uint4*)&smb[grp * 4608 + r * 72 + c * 8] =
            *(const uint4*)&qk[(size_t)(q0g + r) * 128 + c * 8];
    }
#pragma unroll
    for (int i = 0; i < 2; i++) { int idx = tid + 256 * i; int r = idx >> 3, c = idx & 7;
        cpa16(sb + AT_KB + (r * 72 + c * 8) * 2, qk + (size_t)r * 128 + 64 + c * 8); }
#pragma unroll
    for (int i = 0; i < 4; i++) { int idx = tid + 256 * i; int r = idx >> 4, c = idx & 15;
        cpa16(sb + AT_VB + (r * 136 + c * 8) * 2, vsb + (size_t)r * 128 + c * 8); }
    if (tid < 16) cpa16(sb + AT_IB + tid * 16, invp + tid * 4);
    cpcommit();
    __syncthreads();

    int arow = (lane & 7) + ((lane >> 3) & 1) * 8;
    int acol = (lane >> 4) * 8;
    unsigned qbase = sb + gid * 9216;
    unsigned qa_[4][4];
#pragma unroll
    for (int kk2 = 0; kk2 < 4; kk2++)
        ldsm4(qa_[kk2], qbase + ((wg * 16 + arow) * 72 + kk2 * 16 + acol) * 2);

    int krow = ((lane >> 4) << 3) + (lane & 7);
    int kcol = ((lane >> 3) & 1) * 8;

    float acc[16][4] = {};
    int buf = 0;
    int sub = lane >> 3, li = lane & 7;
    for (int tt = 0; tt <= qtB; tt++) {
        if (tt < qtB) {
            int t1 = (tt + 1) * 64, bo = buf ^ 1;
#pragma unroll
            for (int i = 0; i < 2; i++) { int idx = tid + 256 * i; int r = idx >> 3, c = idx & 7;
                cpa16(sb + AT_KB + bo * 9216 + (r * 72 + c * 8) * 2,
                      qk + (size_t)(t1 + r) * 128 + 64 + c * 8); }
#pragma unroll
            for (int i = 0; i < 4; i++) { int idx = tid + 256 * i; int r = idx >> 4, c = idx & 15;
                cpa16(sb + AT_VB + bo * 17408 + (r * 136 + c * 8) * 2,
                      vsb + (size_t)(t1 + r) * 128 + c * 8); }
            if (tid < 16) cpa16(sb + AT_IB + bo * 256 + tid * 16, invp + t1 + tid * 4);
        }
        cpcommit(); cpwait<1>(); __syncthreads();

        if (tt <= myqt) {
            unsigned kbase = sb + AT_KB + buf * 9216;
            float d[8][4] = {};
#pragma unroll
            for (int kk2 = 0; kk2 < 4; kk2++)
#pragma unroll
                for (int nb = 0; nb < 4; nb++) {
                    unsigned r4[4];
                    ldsm4(r4, kbase + ((nb * 16 + krow) * 72 + kk2 * 16 + kcol) * 2);
                    mma16(d[nb * 2 + 0], qa_[kk2], &r4[0]);
                    mma16(d[nb * 2 + 1], qa_[kk2], &r4[2]);
                }
            bool diag = (tt == myqt);
            const float* ivt = invs + buf * 64;
            unsigned Af[4][4];
#pragma unroll
            for (int ni = 0; ni < 8; ni++) {
                float2 iv = *(const float2*)&ivt[ni * 8 + 2 * tg];
                float e[4];
#pragma unroll
                for (int c = 0; c < 4; c++) {
                    int row = wg * 16 + g + (c >> 1) * 8;
                    int col = ni * 8 + 2 * tg + (c & 1);
                    float v = exp2f(d[ni][c]) * ((c & 1) ? iv.y : iv.x);
                    e[c] = (diag && col > row) ? 0.0f : v;
                }
                Af[ni >> 1][(ni & 1) * 2 + 0] = packbf(e[0], e[1]);
                Af[ni >> 1][(ni & 1) * 2 + 1] = packbf(e[2], e[3]);
            }
#pragma unroll
            for (int kc = 0; kc < 4; kc++)
#pragma unroll
                for (int nj = 0; nj < 8; nj++) {
                    unsigned r4[4];
                    unsigned addr = sb + AT_VB + buf * 17408 +
                        ((kc * 16 + (sub & 1) * 8 + li) * 136 + nj * 16 + (sub >> 1) * 8) * 2;
                    ldsm4t(r4, addr);
                    mma16(acc[nj * 2 + 0], Af[kc], &r4[0]);
                    mma16(acc[nj * 2 + 1], Af[kc], &r4[2]);
                }
        }
        __syncthreads();
        buf ^= 1;
    }

    float* stg = gid ? (sm + 8704) : sm;
#pragma unroll
    for (int nj = 0; nj < 16; nj++)
#pragma unroll
        for (int c = 0; c < 4; c++) {
            int row = wg * 16 + g + (c >> 1) * 8;
            int col = nj * 8 + 2 * tg + (c & 1);
            stg[row * 133 + col] = acc[nj][c];
        }
    __syncthreads();
    {
        int gw = tid >> 7, gtid = tid & 127;
        int qq = gtid & 63, db = gtid >> 6;
        const float* s2 = gw ? (sm + 8704) : sm;
        int q0w = gw ? q0B : q0A;
        const float* xin = mb + (size_t)b * ND * NT;
        float* o = out + (size_t)b * ND * NT;
#pragma unroll
        for (int i = 0; i < 64; i++) {
            int d_ = db + i * 2;
            o[d_ * NT + q0w + qq] = xin[d_ * NT + q0w + qq] + s2[qq * 133 + d_];
        }
    }
}

// ---------------------------------------------------------------------------
extern "C" void kernel_launch(void* const* d_in, const int* in_sizes, int n_in,
                              void* d_out, int out_size) {
    const float* mb = (const float*)d_in[0];
    const float* Wk = (const float*)d_in[1];
    const float* bk = (const float*)d_in[2];
    const float* Wq = (const float*)d_in[3];
    const float* bq = (const float*)d_in[4];
    const float* Wv = (const float*)d_in[5];
    const float* bv = (const float*)d_in[6];
    float* out = (float*)d_out;

    cudaFuncSetAttribute(attn_kernel, cudaFuncAttributeMaxDynamicSharedMemorySize, ATT_SMEM);

    qkv_kernel<<<dim3(4, 256), 256>>>(mb, Wq, bq, Wk, bk, Wv, bv);
    colsum_kernel<<<dim3(64, 4, 8), 256>>>();
    attn_kernel<<<dim3(32, 4), 256, ATT_SMEM>>>(mb, out);
}

// round 13
// speedup vs baseline: 1.3613x; 1.0112x over previous
#include <cuda_runtime.h>
#include <cuda_bf16.h>
#include <math.h>

#define NB 4
#define ND 128
#define NT 4096
#define LOG2E 1.4426950408889634f

__device__ __nv_bfloat16 g_QKb[NB * NT * 128];  // per row: [Q(64)*log2e | K(64)] bf16
__device__ __nv_bfloat16 g_Vb[NB * NT * 128];   // V bf16
__device__ float g_colsum[NB * NT];
__device__ float g_inv[NB * NT];                // 1/(8*colsum)
__device__ int   g_cnt[NB * 64];                // per t-tile completion counters

// ---------------------------------------------------------------------------
__device__ __forceinline__ void mma16(float* d, const unsigned* a, const unsigned* b) {
    asm volatile(
        "mma.sync.aligned.m16n8k16.row.col.f32.bf16.bf16.f32 "
        "{%0,%1,%2,%3}, {%4,%5,%6,%7}, {%8,%9}, {%0,%1,%2,%3};\n"
        : "+f"(d[0]), "+f"(d[1]), "+f"(d[2]), "+f"(d[3])
        : "r"(a[0]), "r"(a[1]), "r"(a[2]), "r"(a[3]), "r"(b[0]), "r"(b[1]));
}
__device__ __forceinline__ unsigned packbf(float lo, float hi) {
    unsigned r;
    asm("cvt.rn.bf16x2.f32 %0, %1, %2;" : "=r"(r) : "f"(hi), "f"(lo));
    return r;
}
__device__ __forceinline__ void ldsm4(unsigned* r, unsigned addr) {
    asm volatile("ldmatrix.sync.aligned.m8n8.x4.shared.b16 {%0,%1,%2,%3}, [%4];"
                 : "=r"(r[0]), "=r"(r[1]), "=r"(r[2]), "=r"(r[3]) : "r"(addr));
}
__device__ __forceinline__ void ldsm4t(unsigned* r, unsigned addr) {
    asm volatile("ldmatrix.sync.aligned.m8n8.x4.trans.shared.b16 {%0,%1,%2,%3}, [%4];"
                 : "=r"(r[0]), "=r"(r[1]), "=r"(r[2]), "=r"(r[3]) : "r"(addr));
}
__device__ __forceinline__ void cpa16(unsigned saddr, const void* gsrc) {
    asm volatile("cp.async.cg.shared.global [%0], [%1], 16;" :: "r"(saddr), "l"(gsrc));
}
__device__ __forceinline__ void cpcommit() { asm volatile("cp.async.commit_group;"); }
template <int N>
__device__ __forceinline__ void cpwait() { asm volatile("cp.async.wait_group %0;" :: "n"(N)); }
__device__ __forceinline__ unsigned ldu32(const __nv_bfloat16* p) { return *(const unsigned*)p; }
// swizzled address (bytes): row stride 16 chunks of 16B; chunk XOR'd with row&7
__device__ __forceinline__ unsigned swz(unsigned base, int row, int chunk) {
    return base + ((row * 16 + (chunk ^ (row & 7))) << 4);
}

// ---------------------------------------------------------------------------
// QKV v3: grid (2 n-halves, 512 m-half-tiles). Swizzled bf16 smem, ldmatrix.
// Q output pre-scaled by log2e (attn/colsum use exp2).
__global__ __launch_bounds__(256) void qkv_kernel(const float* __restrict__ mb,
                                                  const float* __restrict__ Wq,
                                                  const float* __restrict__ bq,
                                                  const float* __restrict__ Wk,
                                                  const float* __restrict__ bk,
                                                  const float* __restrict__ Wv,
                                                  const float* __restrict__ bv) {
    __shared__ __align__(16) __nv_bfloat16 Xb[32 * 128];   // swizzled [r][d]
    __shared__ __align__(16) __nv_bfloat16 Wb[128 * 128];  // swizzled [n][d]
    int n0 = blockIdx.x * 128;          // 0 (Q|K) or 128 (V)
    int m0 = blockIdx.y * 32;
    int b = m0 >> 12, t0 = m0 & (NT - 1);
    const float* x = mb + (size_t)b * ND * NT;
    int tid = threadIdx.x, lane = tid & 31, w = tid >> 5;
    int g = lane >> 2, tg = lane & 3;
    int wr = w & 1, wc = w >> 1;        // wr: m16 tile; wc: n32 group (0..3)

    if (blockIdx.x == 0) {              // zero colsum + tile counters
        if (tid < 32) g_colsum[m0 + tid] = 0.0f;
        if (tid == 32 && !(m0 & 32)) g_cnt[m0 >> 6] = 0;
    }

    unsigned xb = (unsigned)__cvta_generic_to_shared(Xb);
    unsigned wb = (unsigned)__cvta_generic_to_shared(Wb);

    // X: 32 r x 64 d2 pairs; global coalesced over r; swizzled conflict-free stores
#pragma unroll
    for (int i = 0; i < 8; i++) {
        int idx = tid + 256 * i;                 // 0..2047
        int r = idx & 31, d2 = idx >> 5;         // d2 0..63
        float v0 = x[(2 * d2) * NT + t0 + r];
        float v1 = x[(2 * d2 + 1) * NT + t0 + r];
        *(unsigned*)&Xb[(r * 16 + ((d2 >> 2) ^ (r & 7))) * 8 + (d2 & 3) * 2] = packbf(v0, v1);
    }
    // W: 128 n-rows x 64 d2 pairs; per-row source select
#pragma unroll
    for (int i = 0; i < 32; i++) {
        int idx = tid + 256 * i;                 // 0..8191
        int d2 = idx & 63, n = idx >> 6;         // n 0..127
        const float* src;
        if (n0 == 0) src = (n < 64) ? &Wq[n * 128] : &Wk[(n - 64) * 128];
        else         src = &Wv[n * 128];
        float2 wv = *(const float2*)&src[2 * d2];
        *(unsigned*)&Wb[(n * 16 + ((d2 >> 2) ^ (n & 7))) * 8 + (d2 & 3) * 2] = packbf(wv.x, wv.y);
    }
    __syncthreads();

    int arow = (lane & 7) + ((lane >> 3) & 1) * 8;
    int achk = lane >> 4;                        // 0..1
    int krow = ((lane >> 4) << 3) + (lane & 7);
    int kchk = (lane >> 3) & 1;

    unsigned qa[8][4];
#pragma unroll
    for (int kk2 = 0; kk2 < 8; kk2++)
        ldsm4(qa[kk2], swz(xb, wr * 16 + arow, kk2 * 2 + achk));

    float acc[4][4] = {};
#pragma unroll
    for (int kk2 = 0; kk2 < 8; kk2++)
#pragma unroll
        for (int nb = 0; nb < 2; nb++) {
            unsigned r4[4];
            ldsm4(r4, swz(wb, wc * 32 + nb * 16 + krow, kk2 * 2 + kchk));
            mma16(acc[nb * 2 + 0], qa[kk2], &r4[0]);
            mma16(acc[nb * 2 + 1], qa[kk2], &r4[2]);
        }

    // epilogue: bias (+ log2e for Q), store bf16
    int nbase = n0 + wc * 32;                    // warp's n range start (32 wide)
    const float* bp; int boff;
    if (nbase < 64)        { bp = bq; boff = 0;   }
    else if (nbase < 128)  { bp = bk; boff = 64;  }
    else                   { bp = bv; boff = 128; }
    float qs = (nbase < 64) ? LOG2E : 1.0f;
#pragma unroll
    for (int ni = 0; ni < 4; ni++) {
        int n = nbase + ni * 8 + 2 * tg;
        float b0 = bp[n - boff], b1 = bp[n + 1 - boff];
        int r1 = m0 + wr * 16 + g, r2 = r1 + 8;
        if (n < 128) {
            *(unsigned*)&g_QKb[(size_t)r1 * 128 + n] =
                packbf((acc[ni][0] + b0) * qs, (acc[ni][1] + b1) * qs);
            *(unsigned*)&g_QKb[(size_t)r2 * 128 + n] =
                packbf((acc[ni][2] + b0) * qs, (acc[ni][3] + b1) * qs);
        } else {
            *(unsigned*)&g_Vb[(size_t)r1 * 128 + n - 128] = packbf(acc[ni][0] + b0, acc[ni][1] + b1);
            *(unsigned*)&g_Vb[(size_t)r2 * 128 + n - 128] = packbf(acc[ni][2] + b0, acc[ni][3] + b1);
        }
    }
}

// ---------------------------------------------------------------------------
// colsum[b][t] = sum_{q>=t} exp2(Q'[q].K[t]); LAST contributing block computes g_inv.
__global__ __launch_bounds__(256) void colsum_kernel() {
    const int QCHUNK = 512;
    int t0 = blockIdx.x * 64, b = blockIdx.y, qlo = blockIdx.z * QCHUNK;
    if (qlo + QCHUNK - 1 < t0) return;
    __shared__ __align__(16) __nv_bfloat16 Ksm[64 * 72];
    __shared__ __align__(16) __nv_bfloat16 Qsm[2][64 * 72];
    __shared__ float cs[64];
    __shared__ int is_last;
    const __nv_bfloat16* qk = g_QKb + (size_t)b * NT * 128;
    int tid = threadIdx.x, lane = tid & 31, w = tid >> 5;
    int g = lane >> 2, tg = lane & 3, wr = w & 1, wc = w >> 1;
    unsigned sbq = (unsigned)__cvta_generic_to_shared(&Qsm[0][0]);

    { int c = tid & 7, r0 = tid >> 3;
#pragma unroll
      for (int i = 0; i < 2; i++) { int r = r0 + 32 * i;
          *(uint4*)&Ksm[r * 72 + c * 8] = *(const uint4*)&qk[(size_t)(t0 + r) * 128 + 64 + c * 8]; } }
    if (tid < 64) cs[tid] = 0.0f;
    { int c = tid & 7, r0 = tid >> 3;
#pragma unroll
      for (int i = 0; i < 2; i++) { int r = r0 + 32 * i;
          cpa16(sbq + (r * 72 + c * 8) * 2, qk + (size_t)(qlo + r) * 128 + c * 8); } }
    cpcommit();
    __syncthreads();

    unsigned bf[2][4][2];
#pragma unroll
    for (int ni = 0; ni < 2; ni++)
#pragma unroll
        for (int kk2 = 0; kk2 < 4; kk2++) {
            int n = wc * 16 + ni * 8 + g;
            bf[ni][kk2][0] = ldu32(&Ksm[n * 72 + kk2 * 16 + 2 * tg]);
            bf[ni][kk2][1] = ldu32(&Ksm[n * 72 + kk2 * 16 + 8 + 2 * tg]);
        }

    float colacc[2][2] = {};
    int buf = 0;
    int arow = (lane & 7) + ((lane >> 3) & 1) * 8;
    int acol = (lane >> 4) * 8;
    for (int q0 = qlo; q0 < qlo + QCHUNK; q0 += 64) {
        if (q0 + 64 < qlo + QCHUNK) {
            int c = tid & 7, r0 = tid >> 3, bo = buf ^ 1;
#pragma unroll
            for (int i = 0; i < 2; i++) { int r = r0 + 32 * i;
                cpa16(sbq + bo * 9216 + (r * 72 + c * 8) * 2,
                      qk + (size_t)(q0 + 64 + r) * 128 + c * 8); }
        }
        cpcommit(); cpwait<1>(); __syncthreads();
        if (q0 + 63 >= t0) {
            unsigned qbase = sbq + buf * 9216;
            float d[2][2][4] = {};
#pragma unroll
            for (int kk2 = 0; kk2 < 4; kk2++) {
                unsigned a[2][4];
#pragma unroll
                for (int mi = 0; mi < 2; mi++) {
                    int r = wr * 32 + mi * 16 + arow;
                    ldsm4(a[mi], qbase + (r * 72 + kk2 * 16 + acol) * 2);
                }
#pragma unroll
                for (int mi = 0; mi < 2; mi++)
#pragma unroll
                    for (int ni = 0; ni < 2; ni++)
                        mma16(d[mi][ni], a[mi], bf[ni][kk2]);
            }
#pragma unroll
            for (int mi = 0; mi < 2; mi++)
#pragma unroll
                for (int ni = 0; ni < 2; ni++)
#pragma unroll
                    for (int e = 0; e < 4; e++) {
                        int row = q0 + wr * 32 + mi * 16 + g + (e >> 1) * 8;
                        int col = t0 + wc * 16 + ni * 8 + 2 * tg + (e & 1);
                        if (row >= col) colacc[ni][e & 1] += exp2f(d[mi][ni][e]);
                    }
        }
        __syncthreads();
        buf ^= 1;
    }
#pragma unroll
    for (int ni = 0; ni < 2; ni++)
#pragma unroll
        for (int j = 0; j < 2; j++) {
            float v = colacc[ni][j];
            v += __shfl_xor_sync(0xffffffffu, v, 4);
            v += __shfl_xor_sync(0xffffffffu, v, 8);
            v += __shfl_xor_sync(0xffffffffu, v, 16);
            colacc[ni][j] = v;
        }
    if (g == 0)
#pragma unroll
        for (int ni = 0; ni < 2; ni++) {
            atomicAdd(&cs[wc * 16 + ni * 8 + 2 * tg], colacc[ni][0]);
            atomicAdd(&cs[wc * 16 + ni * 8 + 2 * tg + 1], colacc[ni][1]);
        }
    __syncthreads();
    if (tid < 64) atomicAdd(&g_colsum[b * NT + t0 + tid], cs[tid]);

    __threadfence();
    __syncthreads();
    if (tid == 0) {
        int n_contrib = 8 - (t0 >> 9);
        int old = atomicAdd(&g_cnt[b * 64 + (t0 >> 6)], 1);
        is_last = (old == n_contrib - 1);
    }
    __syncthreads();
    if (is_last && tid < 64) {
        __threadfence();
        float v = __ldcg(&g_colsum[b * NT + t0 + tid]);
        g_inv[b * NT + t0 + tid] = 1.0f / (8.0f * v);
    }
}

// ---------------------------------------------------------------------------
// attn: block xx handles q-tiles (xx, 63-xx). Warps 0-3 tile A, 4-7 tile B.
#define AT_KB 18432
#define AT_VB 36864
#define AT_IB 71680
#define ATT_SMEM 72192

__global__ __launch_bounds__(256, 1) void attn_kernel(const float* __restrict__ mb,
                                                      float* __restrict__ out) {
    extern __shared__ float sm[];
    __nv_bfloat16* smb = (__nv_bfloat16*)sm;
    float* invs = (float*)((char*)sm + AT_IB);
    int xx = blockIdx.x, b = blockIdx.y;
    int qtA = xx, qtB = 63 - xx;
    int q0A = qtA * 64, q0B = qtB * 64;
    const __nv_bfloat16* qk = g_QKb + (size_t)b * NT * 128;
    const __nv_bfloat16* vsb = g_Vb + (size_t)b * NT * 128;
    const float* invp = g_inv + (size_t)b * NT;
    int tid = threadIdx.x, lane = tid & 31, w = tid >> 5;
    int g = lane >> 2, tg = lane & 3;
    int gid = w >> 2, wg = w & 3;
    int myqt = gid ? qtB : qtA;
    unsigned sb = (unsigned)__cvta_generic_to_shared(sm);

#pragma unroll
    for (int i = 0; i < 4; i++) {
        int idx = tid + 256 * i;
        int grp = idx >> 9, rem = idx & 511, r = rem >> 3, c = rem & 7;
        int q0g = grp ? q0B : q0A;
        *(uint4*)&smb[grp * 4608 + r * 72 + c * 8] =
            *(const uint4*)&qk[(size_t)(q0g + r) * 128 + c * 8];
    }
#pragma unroll
    for (int i = 0; i < 2; i++) { int idx = tid + 256 * i; int r = idx >> 3, c = idx & 7;
        cpa16(sb + AT_KB + (r * 72 + c * 8) * 2, qk + (size_t)r * 128 + 64 + c * 8); }
#pragma unroll
    for (int i = 0; i < 4; i++) { int idx = tid + 256 * i; int r = idx >> 4, c = idx & 15;
        cpa16(sb + AT_VB + (r * 136 + c * 8) * 2, vsb + (size_t)r * 128 + c * 8); }
    if (tid < 16) cpa16(sb + AT_IB + tid * 16, invp + tid * 4);
    cpcommit();
    __syncthreads();

    int arow = (lane & 7) + ((lane >> 3) & 1) * 8;
    int acol = (lane >> 4) * 8;
    unsigned qbase = sb + gid * 9216;
    unsigned qa_[4][4];
#pragma unroll
    for (int kk2 = 0; kk2 < 4; kk2++)
        ldsm4(qa_[kk2], qbase + ((wg * 16 + arow) * 72 + kk2 * 16 + acol) * 2);

    int krow = ((lane >> 4) << 3) + (lane & 7);
    int kcol = ((lane >> 3) & 1) * 8;

    float acc[16][4] = {};
    int buf = 0;
    int sub = lane >> 3, li = lane & 7;
    for (int tt = 0; tt <= qtB; tt++) {
        if (tt < qtB) {
            int t1 = (tt + 1) * 64, bo = buf ^ 1;
#pragma unroll
            for (int i = 0; i < 2; i++) { int idx = tid + 256 * i; int r = idx >> 3, c = idx & 7;
                cpa16(sb + AT_KB + bo * 9216 + (r * 72 + c * 8) * 2,
                      qk + (size_t)(t1 + r) * 128 + 64 + c * 8); }
#pragma unroll
            for (int i = 0; i < 4; i++) { int idx = tid + 256 * i; int r = idx >> 4, c = idx & 15;
                cpa16(sb + AT_VB + bo * 17408 + (r * 136 + c * 8) * 2,
                      vsb + (size_t)(t1 + r) * 128 + c * 8); }
            if (tid < 16) cpa16(sb + AT_IB + bo * 256 + tid * 16, invp + t1 + tid * 4);
        }
        cpcommit(); cpwait<1>(); __syncthreads();

        if (tt <= myqt) {
            unsigned kbase = sb + AT_KB + buf * 9216;
            float d[8][4] = {};
#pragma unroll
            for (int kk2 = 0; kk2 < 4; kk2++)
#pragma unroll
                for (int nb = 0; nb < 4; nb++) {
                    unsigned r4[4];
                    ldsm4(r4, kbase + ((nb * 16 + krow) * 72 + kk2 * 16 + kcol) * 2);
                    mma16(d[nb * 2 + 0], qa_[kk2], &r4[0]);
                    mma16(d[nb * 2 + 1], qa_[kk2], &r4[2]);
                }
            bool diag = (tt == myqt);
            const float* ivt = invs + buf * 64;
            unsigned Af[4][4];
#pragma unroll
            for (int ni = 0; ni < 8; ni++) {
                float2 iv = *(const float2*)&ivt[ni * 8 + 2 * tg];
                float e[4];
#pragma unroll
                for (int c = 0; c < 4; c++) {
                    int row = wg * 16 + g + (c >> 1) * 8;
                    int col = ni * 8 + 2 * tg + (c & 1);
                    float v = exp2f(d[ni][c]) * ((c & 1) ? iv.y : iv.x);
                    e[c] = (diag && col > row) ? 0.0f : v;
                }
                Af[ni >> 1][(ni & 1) * 2 + 0] = packbf(e[0], e[1]);
                Af[ni >> 1][(ni & 1) * 2 + 1] = packbf(e[2], e[3]);
            }
#pragma unroll
            for (int kc = 0; kc < 4; kc++)
#pragma unroll
                for (int nj = 0; nj < 8; nj++) {
                    unsigned r4[4];
                    unsigned addr = sb + AT_VB + buf * 17408 +
                        ((kc * 16 + (sub & 1) * 8 + li) * 136 + nj * 16 + (sub >> 1) * 8) * 2;
                    ldsm4t(r4, addr);
                    mma16(acc[nj * 2 + 0], Af[kc], &r4[0]);
                    mma16(acc[nj * 2 + 1], Af[kc], &r4[2]);
                }
        }
        __syncthreads();
        buf ^= 1;
    }

    float* stg = gid ? (sm + 8704) : sm;
#pragma unroll
    for (int nj = 0; nj < 16; nj++)
#pragma unroll
        for (int c = 0; c < 4; c++) {
            int row = wg * 16 + g + (c >> 1) * 8;
            int col = nj * 8 + 2 * tg + (c & 1);
            stg[row * 133 + col] = acc[nj][c];
        }
    __syncthreads();
    {
        int gw = tid >> 7, gtid = tid & 127;
        int qq = gtid & 63, db = gtid >> 6;
        const float* s2 = gw ? (sm + 8704) : sm;
        int q0w = gw ? q0B : q0A;
        const float* xin = mb + (size_t)b * ND * NT;
        float* o = out + (size_t)b * ND * NT;
#pragma unroll
        for (int i = 0; i < 64; i++) {
            int d_ = db + i * 2;
            o[d_ * NT + q0w + qq] = xin[d_ * NT + q0w + qq] + s2[qq * 133 + d_];
        }
    }
}

// ---------------------------------------------------------------------------
extern "C" void kernel_launch(void* const* d_in, const int* in_sizes, int n_in,
                              void* d_out, int out_size) {
    const float* mb = (const float*)d_in[0];
    const float* Wk = (const float*)d_in[1];
    const float* bk = (const float*)d_in[2];
    const float* Wq = (const float*)d_in[3];
    const float* bq = (const float*)d_in[4];
    const float* Wv = (const float*)d_in[5];
    const float* bv = (const float*)d_in[6];
    float* out = (float*)d_out;

    cudaFuncSetAttribute(attn_kernel, cudaFuncAttributeMaxDynamicSharedMemorySize, ATT_SMEM);

    qkv_kernel<<<dim3(2, 512), 256>>>(mb, Wq, bq, Wk, bk, Wv, bv);
    colsum_kernel<<<dim3(64, 4, 8), 256>>>();
    attn_kernel<<<dim3(32, 4), 256, ATT_SMEM>>>(mb, out);
}

// round 14
// speedup vs baseline: 1.3925x; 1.0229x over previous
#include <cuda_runtime.h>
#include <cuda_bf16.h>
#include <math.h>

#define NB 4
#define ND 128
#define NT 4096
#define LOG2E 1.4426950408889634f

__device__ __nv_bfloat16 g_QKb[NB * NT * 128];  // per row: [Q(64)*log2e | K(64)] bf16
__device__ __nv_bfloat16 g_Vb[NB * NT * 128];   // V bf16
__device__ __nv_bfloat16 g_Wb[256 * 128];       // [Wq*log2e | Wk | Wv] bf16
__device__ float g_biasf[256];                  // [bq*log2e | bk | bv]
__device__ float g_colsum[NB * NT];
__device__ float g_inv[NB * NT];                // 1/(8*colsum)
__device__ int   g_cnt[NB * 64];                // per t-tile completion counters

// ---------------------------------------------------------------------------
__device__ __forceinline__ void mma16(float* d, const unsigned* a, const unsigned* b) {
    asm volatile(
        "mma.sync.aligned.m16n8k16.row.col.f32.bf16.bf16.f32 "
        "{%0,%1,%2,%3}, {%4,%5,%6,%7}, {%8,%9}, {%0,%1,%2,%3};\n"
        : "+f"(d[0]), "+f"(d[1]), "+f"(d[2]), "+f"(d[3])
        : "r"(a[0]), "r"(a[1]), "r"(a[2]), "r"(a[3]), "r"(b[0]), "r"(b[1]));
}
__device__ __forceinline__ unsigned packbf(float lo, float hi) {
    unsigned r;
    asm("cvt.rn.bf16x2.f32 %0, %1, %2;" : "=r"(r) : "f"(hi), "f"(lo));
    return r;
}
__device__ __forceinline__ void ldsm4(unsigned* r, unsigned addr) {
    asm volatile("ldmatrix.sync.aligned.m8n8.x4.shared.b16 {%0,%1,%2,%3}, [%4];"
                 : "=r"(r[0]), "=r"(r[1]), "=r"(r[2]), "=r"(r[3]) : "r"(addr));
}
__device__ __forceinline__ void ldsm4t(unsigned* r, unsigned addr) {
    asm volatile("ldmatrix.sync.aligned.m8n8.x4.trans.shared.b16 {%0,%1,%2,%3}, [%4];"
                 : "=r"(r[0]), "=r"(r[1]), "=r"(r[2]), "=r"(r[3]) : "r"(addr));
}
__device__ __forceinline__ void cpa16(unsigned saddr, const void* gsrc) {
    asm volatile("cp.async.cg.shared.global [%0], [%1], 16;" :: "r"(saddr), "l"(gsrc));
}
__device__ __forceinline__ void cpcommit() { asm volatile("cp.async.commit_group;"); }
template <int N>
__device__ __forceinline__ void cpwait() { asm volatile("cp.async.wait_group %0;" :: "n"(N)); }
__device__ __forceinline__ unsigned ldu32(const __nv_bfloat16* p) { return *(const unsigned*)p; }
// swizzled address (bytes): row stride 16 chunks of 16B; chunk XOR'd with row&7
__device__ __forceinline__ unsigned swz(unsigned base, int row, int chunk) {
    return base + ((row * 16 + (chunk ^ (row & 7))) << 4);
}

// ---------------------------------------------------------------------------
// Convert weights to bf16 once; fold log2e into Wq/bq.
__global__ void wconv_kernel(const float* __restrict__ Wq, const float* __restrict__ bq,
                             const float* __restrict__ Wk, const float* __restrict__ bk,
                             const float* __restrict__ Wv, const float* __restrict__ bv) {
    int i = blockIdx.x * 256 + threadIdx.x;      // [0, 32768)
    int n = i >> 7, d = i & 127;
    float v;
    if (n < 64)       v = Wq[n * 128 + d] * LOG2E;
    else if (n < 128) v = Wk[(n - 64) * 128 + d];
    else              v = Wv[(n - 128) * 128 + d];
    g_Wb[i] = __float2bfloat16(v);
    if (i < 256) {
        float bb;
        if (i < 64)       bb = bq[i] * LOG2E;
        else if (i < 128) bb = bk[i - 64];
        else              bb = bv[i - 128];
        g_biasf[i] = bb;
    }
}

// ---------------------------------------------------------------------------
// QKV: grid (2 n-halves, 512 m-half-tiles). W via cp.async (preconverted bf16).
__global__ __launch_bounds__(256) void qkv_kernel(const float* __restrict__ mb) {
    __shared__ __align__(16) __nv_bfloat16 Xb[32 * 128];   // swizzled [r][d]
    __shared__ __align__(16) __nv_bfloat16 Wb[128 * 128];  // swizzled [n][d]
    int n0 = blockIdx.x * 128;          // 0 (Q|K) or 128 (V)
    int m0 = blockIdx.y * 32;
    int b = m0 >> 12, t0 = m0 & (NT - 1);
    const float* x = mb + (size_t)b * ND * NT;
    int tid = threadIdx.x, lane = tid & 31, w = tid >> 5;
    int g = lane >> 2, tg = lane & 3;
    int wr = w & 1, wc = w >> 1;        // wr: m16 tile; wc: n32 group (0..3)

    if (blockIdx.x == 0) {              // zero colsum + tile counters
        if (tid < 32) g_colsum[m0 + tid] = 0.0f;
        if (tid == 32 && !(m0 & 32)) g_cnt[m0 >> 6] = 0;
    }

    unsigned xb = (unsigned)__cvta_generic_to_shared(Xb);
    unsigned wb = (unsigned)__cvta_generic_to_shared(Wb);

    // W tile: cp.async bf16 into swizzled layout (16B = 8 d-elements per chunk)
#pragma unroll
    for (int i = 0; i < 8; i++) {
        int idx = tid + 256 * i;                 // 0..2047
        int n = idx >> 4, c = idx & 15;
        cpa16(swz(wb, n, c), &g_Wb[(size_t)(n0 + n) * 128 + c * 8]);
    }
    cpcommit();

    // X: 32 r x 64 d2 pairs; global coalesced over r; swizzled conflict-free stores
#pragma unroll
    for (int i = 0; i < 8; i++) {
        int idx = tid + 256 * i;                 // 0..2047
        int r = idx & 31, d2 = idx >> 5;         // d2 0..63
        float v0 = x[(2 * d2) * NT + t0 + r];
        float v1 = x[(2 * d2 + 1) * NT + t0 + r];
        *(unsigned*)&Xb[(r * 16 + ((d2 >> 2) ^ (r & 7))) * 8 + (d2 & 3) * 2] = packbf(v0, v1);
    }
    cpwait<0>();
    __syncthreads();

    int arow = (lane & 7) + ((lane >> 3) & 1) * 8;
    int achk = lane >> 4;                        // 0..1
    int krow = ((lane >> 4) << 3) + (lane & 7);
    int kchk = (lane >> 3) & 1;

    unsigned qa[8][4];
#pragma unroll
    for (int kk2 = 0; kk2 < 8; kk2++)
        ldsm4(qa[kk2], swz(xb, wr * 16 + arow, kk2 * 2 + achk));

    float acc[4][4] = {};
#pragma unroll
    for (int kk2 = 0; kk2 < 8; kk2++)
#pragma unroll
        for (int nb = 0; nb < 2; nb++) {
            unsigned r4[4];
            ldsm4(r4, swz(wb, wc * 32 + nb * 16 + krow, kk2 * 2 + kchk));
            mma16(acc[nb * 2 + 0], qa[kk2], &r4[0]);
            mma16(acc[nb * 2 + 1], qa[kk2], &r4[2]);
        }

    // epilogue: bias, store bf16 (log2e already folded into Wq/bq)
    int nbase = n0 + wc * 32;
#pragma unroll
    for (int ni = 0; ni < 4; ni++) {
        int n = nbase + ni * 8 + 2 * tg;
        float b0 = g_biasf[n], b1 = g_biasf[n + 1];
        int r1 = m0 + wr * 16 + g, r2 = r1 + 8;
        if (n < 128) {
            *(unsigned*)&g_QKb[(size_t)r1 * 128 + n] = packbf(acc[ni][0] + b0, acc[ni][1] + b1);
            *(unsigned*)&g_QKb[(size_t)r2 * 128 + n] = packbf(acc[ni][2] + b0, acc[ni][3] + b1);
        } else {
            *(unsigned*)&g_Vb[(size_t)r1 * 128 + n - 128] = packbf(acc[ni][0] + b0, acc[ni][1] + b1);
            *(unsigned*)&g_Vb[(size_t)r2 * 128 + n - 128] = packbf(acc[ni][2] + b0, acc[ni][3] + b1);
        }
    }
}

// ---------------------------------------------------------------------------
// colsum[b][t] = sum_{q>=t} exp2(Q'[q].K[t]); LAST contributing block computes g_inv.
__global__ __launch_bounds__(256) void colsum_kernel() {
    const int QCHUNK = 512;
    int t0 = blockIdx.x * 64, b = blockIdx.y, qlo = blockIdx.z * QCHUNK;
    if (qlo + QCHUNK - 1 < t0) return;
    __shared__ __align__(16) __nv_bfloat16 Ksm[64 * 72];
    __shared__ __align__(16) __nv_bfloat16 Qsm[2][64 * 72];
    __shared__ float cs[64];
    __shared__ int is_last;
    const __nv_bfloat16* qk = g_QKb + (size_t)b * NT * 128;
    int tid = threadIdx.x, lane = tid & 31, w = tid >> 5;
    int g = lane >> 2, tg = lane & 3, wr = w & 1, wc = w >> 1;
    unsigned sbq = (unsigned)__cvta_generic_to_shared(&Qsm[0][0]);

    { int c = tid & 7, r0 = tid >> 3;
#pragma unroll
      for (int i = 0; i < 2; i++) { int r = r0 + 32 * i;
          *(uint4*)&Ksm[r * 72 + c * 8] = *(const uint4*)&qk[(size_t)(t0 + r) * 128 + 64 + c * 8]; } }
    if (tid < 64) cs[tid] = 0.0f;
    { int c = tid & 7, r0 = tid >> 3;
#pragma unroll
      for (int i = 0; i < 2; i++) { int r = r0 + 32 * i;
          cpa16(sbq + (r * 72 + c * 8) * 2, qk + (size_t)(qlo + r) * 128 + c * 8); } }
    cpcommit();
    __syncthreads();

    unsigned bf[2][4][2];
#pragma unroll
    for (int ni = 0; ni < 2; ni++)
#pragma unroll
        for (int kk2 = 0; kk2 < 4; kk2++) {
            int n = wc * 16 + ni * 8 + g;
            bf[ni][kk2][0] = ldu32(&Ksm[n * 72 + kk2 * 16 + 2 * tg]);
            bf[ni][kk2][1] = ldu32(&Ksm[n * 72 + kk2 * 16 + 8 + 2 * tg]);
        }

    float colacc[2][2] = {};
    int buf = 0;
    int arow = (lane & 7) + ((lane >> 3) & 1) * 8;
    int acol = (lane >> 4) * 8;
    for (int q0 = qlo; q0 < qlo + QCHUNK; q0 += 64) {
        if (q0 + 64 < qlo + QCHUNK) {
            int c = tid & 7, r0 = tid >> 3, bo = buf ^ 1;
#pragma unroll
            for (int i = 0; i < 2; i++) { int r = r0 + 32 * i;
                cpa16(sbq + bo * 9216 + (r * 72 + c * 8) * 2,
                      qk + (size_t)(q0 + 64 + r) * 128 + c * 8); }
        }
        cpcommit(); cpwait<1>(); __syncthreads();
        if (q0 + 63 >= t0) {
            unsigned qbase = sbq + buf * 9216;
            float d[2][2][4] = {};
#pragma unroll
            for (int kk2 = 0; kk2 < 4; kk2++) {
                unsigned a[2][4];
#pragma unroll
                for (int mi = 0; mi < 2; mi++) {
                    int r = wr * 32 + mi * 16 + arow;
                    ldsm4(a[mi], qbase + (r * 72 + kk2 * 16 + acol) * 2);
                }
#pragma unroll
                for (int mi = 0; mi < 2; mi++)
#pragma unroll
                    for (int ni = 0; ni < 2; ni++)
                        mma16(d[mi][ni], a[mi], bf[ni][kk2]);
            }
#pragma unroll
            for (int mi = 0; mi < 2; mi++)
#pragma unroll
                for (int ni = 0; ni < 2; ni++)
#pragma unroll
                    for (int e = 0; e < 4; e++) {
                        int row = q0 + wr * 32 + mi * 16 + g + (e >> 1) * 8;
                        int col = t0 + wc * 16 + ni * 8 + 2 * tg + (e & 1);
                        if (row >= col) colacc[ni][e & 1] += exp2f(d[mi][ni][e]);
                    }
        }
        __syncthreads();
        buf ^= 1;
    }
#pragma unroll
    for (int ni = 0; ni < 2; ni++)
#pragma unroll
        for (int j = 0; j < 2; j++) {
            float v = colacc[ni][j];
            v += __shfl_xor_sync(0xffffffffu, v, 4);
            v += __shfl_xor_sync(0xffffffffu, v, 8);
            v += __shfl_xor_sync(0xffffffffu, v, 16);
            colacc[ni][j] = v;
        }
    if (g == 0)
#pragma unroll
        for (int ni = 0; ni < 2; ni++) {
            atomicAdd(&cs[wc * 16 + ni * 8 + 2 * tg], colacc[ni][0]);
            atomicAdd(&cs[wc * 16 + ni * 8 + 2 * tg + 1], colacc[ni][1]);
        }
    __syncthreads();
    if (tid < 64) atomicAdd(&g_colsum[b * NT + t0 + tid], cs[tid]);

    __threadfence();
    __syncthreads();
    if (tid == 0) {
        int n_contrib = 8 - (t0 >> 9);
        int old = atomicAdd(&g_cnt[b * 64 + (t0 >> 6)], 1);
        is_last = (old == n_contrib - 1);
    }
    __syncthreads();
    if (is_last && tid < 64) {
        __threadfence();
        float v = __ldcg(&g_colsum[b * NT + t0 + tid]);
        g_inv[b * NT + t0 + tid] = 1.0f / (8.0f * v);
    }
}

// ---------------------------------------------------------------------------
// attn: block xx handles q-tiles (xx, 63-xx). Warps 0-3 tile A, 4-7 tile B.
#define AT_KB 18432
#define AT_VB 36864
#define AT_IB 71680
#define ATT_SMEM 72192

__global__ __launch_bounds__(256, 1) void attn_kernel(const float* __restrict__ mb,
                                                      float* __restrict__ out) {
    extern __shared__ float sm[];
    __nv_bfloat16* smb = (__nv_bfloat16*)sm;
    float* invs = (float*)((char*)sm + AT_IB);
    int xx = blockIdx.x, b = blockIdx.y;
    int qtA = xx, qtB = 63 - xx;
    int q0A = qtA * 64, q0B = qtB * 64;
    const __nv_bfloat16* qk = g_QKb + (size_t)b * NT * 128;
    const __nv_bfloat16* vsb = g_Vb + (size_t)b * NT * 128;
    const float* invp = g_inv + (size_t)b * NT;
    int tid = threadIdx.x, lane = tid & 31, w = tid >> 5;
    int g = lane >> 2, tg = lane & 3;
    int gid = w >> 2, wg = w & 3;
    int myqt = gid ? qtB : qtA;
    unsigned sb = (unsigned)__cvta_generic_to_shared(sm);

#pragma unroll
    for (int i = 0; i < 4; i++) {
        int idx = tid + 256 * i;
        int grp = idx >> 9, rem = idx & 511, r = rem >> 3, c = rem & 7;
        int q0g = grp ? q0B : q0A;
        *(uint4*)&smb[grp * 4608 + r * 72 + c * 8] =
            *(const uint4*)&qk[(size_t)(q0g + r) * 128 + c * 8];
    }
#pragma unroll
    for (int i = 0; i < 2; i++) { int idx = tid + 256 * i; int r = idx >> 3, c = idx & 7;
        cpa16(sb + AT_KB + (r * 72 + c * 8) * 2, qk + (size_t)r * 128 + 64 + c * 8); }
#pragma unroll
    for (int i = 0; i < 4; i++) { int idx = tid + 256 * i; int r = idx >> 4, c = idx & 15;
        cpa16(sb + AT_VB + (r * 136 + c * 8) * 2, vsb + (size_t)r * 128 + c * 8); }
    if (tid < 16) cpa16(sb + AT_IB + tid * 16, invp + tid * 4);
    cpcommit();
    __syncthreads();

    int arow = (lane & 7) + ((lane >> 3) & 1) * 8;
    int acol = (lane >> 4) * 8;
    unsigned qbase = sb + gid * 9216;
    unsigned qa_[4][4];
#pragma unroll
    for (int kk2 = 0; kk2 < 4; kk2++)
        ldsm4(qa_[kk2], qbase + ((wg * 16 + arow) * 72 + kk2 * 16 + acol) * 2);

    int krow = ((lane >> 4) << 3) + (lane & 7);
    int kcol = ((lane >> 3) & 1) * 8;

    float acc[16][4] = {};
    int buf = 0;
    int sub = lane >> 3, li = lane & 7;
    for (int tt = 0; tt <= qtB; tt++) {
        if (tt < qtB) {
            int t1 = (tt + 1) * 64, bo = buf ^ 1;
#pragma unroll
            for (int i = 0; i < 2; i++) { int idx = tid + 256 * i; int r = idx >> 3, c = idx & 7;
                cpa16(sb + AT_KB + bo * 9216 + (r * 72 + c * 8) * 2,
                      qk + (size_t)(t1 + r) * 128 + 64 + c * 8); }
#pragma unroll
            for (int i = 0; i < 4; i++) { int idx = tid + 256 * i; int r = idx >> 4, c = idx & 15;
                cpa16(sb + AT_VB + bo * 17408 + (r * 136 + c * 8) * 2,
                      vsb + (size_t)(t1 + r) * 128 + c * 8); }
            if (tid < 16) cpa16(sb + AT_IB + bo * 256 + tid * 16, invp + t1 + tid * 4);
        }
        cpcommit(); cpwait<1>(); __syncthreads();

        if (tt <= myqt) {
            unsigned kbase = sb + AT_KB + buf * 9216;
            float d[8][4] = {};
#pragma unroll
            for (int kk2 = 0; kk2 < 4; kk2++)
#pragma unroll
                for (int nb = 0; nb < 4; nb++) {
                    unsigned r4[4];
                    ldsm4(r4, kbase + ((nb * 16 + krow) * 72 + kk2 * 16 + kcol) * 2);
                    mma16(d[nb * 2 + 0], qa_[kk2], &r4[0]);
                    mma16(d[nb * 2 + 1], qa_[kk2], &r4[2]);
                }
            bool diag = (tt == myqt);
            const float* ivt = invs + buf * 64;
            unsigned Af[4][4];
#pragma unroll
            for (int ni = 0; ni < 8; ni++) {
                float2 iv = *(const float2*)&ivt[ni * 8 + 2 * tg];
                float e[4];
#pragma unroll
                for (int c = 0; c < 4; c++) {
                    int row = wg * 16 + g + (c >> 1) * 8;
                    int col = ni * 8 + 2 * tg + (c & 1);
                    float v = exp2f(d[ni][c]) * ((c & 1) ? iv.y : iv.x);
                    e[c] = (diag && col > row) ? 0.0f : v;
                }
                Af[ni >> 1][(ni & 1) * 2 + 0] = packbf(e[0], e[1]);
                Af[ni >> 1][(ni & 1) * 2 + 1] = packbf(e[2], e[3]);
            }
#pragma unroll
            for (int kc = 0; kc < 4; kc++)
#pragma unroll
                for (int nj = 0; nj < 8; nj++) {
                    unsigned r4[4];
                    unsigned addr = sb + AT_VB + buf * 17408 +
                        ((kc * 16 + (sub & 1) * 8 + li) * 136 + nj * 16 + (sub >> 1) * 8) * 2;
                    ldsm4t(r4, addr);
                    mma16(acc[nj * 2 + 0], Af[kc], &r4[0]);
                    mma16(acc[nj * 2 + 1], Af[kc], &r4[2]);
                }
        }
        __syncthreads();
        buf ^= 1;
    }

    float* stg = gid ? (sm + 8704) : sm;
#pragma unroll
    for (int nj = 0; nj < 16; nj++)
#pragma unroll
        for (int c = 0; c < 4; c++) {
            int row = wg * 16 + g + (c >> 1) * 8;
            int col = nj * 8 + 2 * tg + (c & 1);
            stg[row * 133 + col] = acc[nj][c];
        }
    __syncthreads();
    {
        int gw = tid >> 7, gtid = tid & 127;
        int qq = gtid & 63, db = gtid >> 6;
        const float* s2 = gw ? (sm + 8704) : sm;
        int q0w = gw ? q0B : q0A;
        const float* xin = mb + (size_t)b * ND * NT;
        float* o = out + (size_t)b * ND * NT;
#pragma unroll
        for (int i = 0; i < 64; i++) {
            int d_ = db + i * 2;
            o[d_ * NT + q0w + qq] = xin[d_ * NT + q0w + qq] + s2[qq * 133 + d_];
        }
    }
}

// ---------------------------------------------------------------------------
extern "C" void kernel_launch(void* const* d_in, const int* in_sizes, int n_in,
                              void* d_out, int out_size) {
    const float* mb = (const float*)d_in[0];
    const float* Wk = (const float*)d_in[1];
    const float* bk = (const float*)d_in[2];
    const float* Wq = (const float*)d_in[3];
    const float* bq = (const float*)d_in[4];
    const float* Wv = (const float*)d_in[5];
    const float* bv = (const float*)d_in[6];
    float* out = (float*)d_out;

    cudaFuncSetAttribute(attn_kernel, cudaFuncAttributeMaxDynamicSharedMemorySize, ATT_SMEM);

    wconv_kernel<<<128, 256>>>(Wq, bq, Wk, bk, Wv, bv);
    qkv_kernel<<<dim3(2, 512), 256>>>(mb);
    colsum_kernel<<<dim3(64, 4, 8), 256>>>();
    attn_kernel<<<dim3(32, 4), 256, ATT_SMEM>>>(mb, out);
}